// round 2
// baseline (speedup 1.0000x reference)
#include <cuda_runtime.h>
#include <cstdint>

#define B_TOTAL   8192
#define JDIM      784
#define HDIM      1024
#define ODIM      10
#define TSTEPS    50
#define BM        32
#define NTHREADS  256
#define KB        16
#define NKB       (JDIM / KB)      // 49
#define THRESH_F  0.5f
#define DECAY_F   0.2f

// Transposed W1: [784][1024] so per-j weight rows are contiguous (coalesced staging,
// broadcast LDS.128 in the inner loop). 3.2 MB static device scratch (no allocs).
__device__ float g_W1t[JDIM * HDIM];

// ---------------------------------------------------------------------------
// One-off (per launch) transpose W1 [1024,784] -> g_W1t [784,1024]
// ---------------------------------------------------------------------------
__global__ void transpose_w1_kernel(const float* __restrict__ W1) {
    __shared__ float tile[32][33];
    const int jb = blockIdx.x * 32;
    const int hb = blockIdx.y * 32;
    const int tx = threadIdx.x, ty = threadIdx.y;
    #pragma unroll
    for (int i = 0; i < 32; i += 8) {
        int h = hb + ty + i, j = jb + tx;
        float v = 0.0f;
        if (h < HDIM && j < JDIM) v = W1[h * JDIM + j];
        tile[ty + i][tx] = v;
    }
    __syncthreads();
    #pragma unroll
    for (int i = 0; i < 32; i += 8) {
        int j = jb + ty + i, h = hb + tx;
        if (j < JDIM && h < HDIM) g_W1t[j * HDIM + h] = tile[tx][ty + i];
    }
}

// ---------------------------------------------------------------------------
// Packed fp32x2 helpers (Blackwell packed-FP32 pipe; 2x scalar FADD throughput)
// ---------------------------------------------------------------------------
#define FMA_F32X2(acc, x, w) \
    asm("fma.rn.f32x2 %0, %1, %2, %0;" : "+l"(acc) : "l"(x), "l"(w))
#define MUL_F32X2(d, a, b) \
    asm("mul.rn.f32x2 %0, %1, %2;" : "=l"(d) : "l"(a), "l"(b))

// ---------------------------------------------------------------------------
// Main fused SNN kernel. One CTA owns BM=32 batch rows for all 50 timesteps.
// m1 state lives in registers as 64 packed f32x2 accumulators per thread:
//   row  = lane (0..31), cols = [wid*128, wid*128+128) packed in col-pairs.
// ---------------------------------------------------------------------------
__global__ __launch_bounds__(NTHREADS, 1)
void snn_kernel(const float* __restrict__ sample,   // [8192,784]
                const float* __restrict__ rand_u,   // [50,8192,784]
                const float* __restrict__ W2,       // [10,1024]
                float* __restrict__ out)            // [8192,10]
{
    extern __shared__ char smem_raw[];
    float*    w_tile  = (float*)smem_raw;                       // KB*HDIM      (64 KB)
    float*    W2s     = w_tile + KB * HDIM;                     // ODIM*HDIM    (40 KB)
    unsigned* x_mask  = (unsigned*)(W2s + ODIM * HDIM);         // BM*27        (3.4 KB)
    unsigned* s1_mask = x_mask + BM * 27;                       // BM*32        (4 KB)
    float*    m2s     = (float*)(s1_mask + BM * 32);            // BM*ODIM
    float*    ss      = m2s + BM * ODIM;                        // BM*ODIM

    const int tid  = threadIdx.x;
    const int lane = tid & 31;
    const int wid  = tid >> 5;                    // 0..7
    const int rowbase = blockIdx.x * BM;

    // Stage W2 into smem; zero m2 / sumspike
    for (int i = tid; i < ODIM * HDIM; i += NTHREADS) W2s[i] = W2[i];
    for (int i = tid; i < BM * ODIM; i += NTHREADS) { m2s[i] = 0.0f; ss[i] = 0.0f; }

    unsigned long long acc[64];
    #pragma unroll
    for (int i = 0; i < 64; i++) acc[i] = 0ull;

    const int cbase = wid * 128;
    const unsigned long long ONE2 = 0x3F8000003F800000ull;   // (1.0f, 1.0f)
    const unsigned long long DEC2 = 0x3E4CCCCD3E4CCCCDull;   // (0.2f, 0.2f)

    const float* samp_row = sample + (size_t)rowbase * JDIM;

    __syncthreads();

    for (int t = 0; t < TSTEPS; t++) {
        // ---------- phase 1: x = (sample > rand) as bitmask via ballot ----------
        const float* rnd = rand_u + ((size_t)t * B_TOTAL + rowbase) * JDIM;
        for (int k = wid; k < BM * 25; k += 8) {
            int r = k / 25, wd = k % 25;
            int j = wd * 32 + lane;
            bool bit = false;
            if (j < JDIM) bit = samp_row[r * JDIM + j] > rnd[r * JDIM + j];
            unsigned m = __ballot_sync(0xffffffffu, bit);
            if (lane == 0) x_mask[r * 27 + wd] = m;
        }
        // membrane decay on register-resident m1 (post-reset value from prev step)
        #pragma unroll
        for (int i = 0; i < 64; i++) MUL_F32X2(acc[i], acc[i], DEC2);
        __syncthreads();

        // ---------- phase 2: m1 += x @ W1^T  (branch-free packed FMA) ----------
        for (int kb = 0; kb < NKB; kb++) {
            {   // cooperative stage of 16 j-rows of W1t (coalesced float4)
                const float4* src = (const float4*)(g_W1t + (size_t)kb * KB * HDIM);
                float4* dst = (float4*)w_tile;
                #pragma unroll
                for (int i = 0; i < (KB * HDIM / 4) / NTHREADS; i++)
                    dst[tid + i * NTHREADS] = src[tid + i * NTHREADS];
            }
            __syncthreads();
            #pragma unroll
            for (int jj = 0; jj < KB; jj++) {
                const int j = kb * KB + jj;
                const unsigned word = x_mask[lane * 27 + (j >> 5)];
                const unsigned long long x2 = ((word >> (j & 31)) & 1u) ? ONE2 : 0ull;
                const ulonglong2* wrow = (const ulonglong2*)(&w_tile[jj * HDIM + cbase]);
                #pragma unroll
                for (int p = 0; p < 32; p++) {
                    ulonglong2 w2 = wrow[p];           // broadcast LDS.128 (4 floats)
                    FMA_F32X2(acc[2 * p],     x2, w2.x);
                    FMA_F32X2(acc[2 * p + 1], x2, w2.y);
                }
            }
            __syncthreads();
        }

        // ---------- phase 3: s1 = m1 > 0.5, reset-on-spike, pack bitmask ----------
        #pragma unroll
        for (int wd = 0; wd < 4; wd++) {
            unsigned bits = 0;
            #pragma unroll
            for (int p = 0; p < 16; p++) {
                const int pi = wd * 16 + p;
                float flo = __uint_as_float((unsigned)(acc[pi] & 0xffffffffull));
                float fhi = __uint_as_float((unsigned)(acc[pi] >> 32));
                if (flo > THRESH_F) { bits |= 1u << (2 * p);     flo = 0.0f; }
                if (fhi > THRESH_F) { bits |= 1u << (2 * p + 1); fhi = 0.0f; }
                acc[pi] = ((unsigned long long)__float_as_uint(fhi) << 32) |
                          (unsigned long long)__float_as_uint(flo);
            }
            s1_mask[lane * 32 + (wid * 4 + wd)] = bits;
        }
        __syncthreads();

        // ---------- phase 4: layer 2 (warp per row, masked adds + shfl reduce) ----------
        #pragma unroll
        for (int rr = 0; rr < 4; rr++) {
            const int r = wid * 4 + rr;
            float dot[ODIM];
            #pragma unroll
            for (int o = 0; o < ODIM; o++) dot[o] = 0.0f;
            #pragma unroll 4
            for (int k = 0; k < 32; k++) {
                const unsigned wmask = s1_mask[r * 32 + k];
                if ((wmask >> lane) & 1u) {
                    const int h = k * 32 + lane;
                    #pragma unroll
                    for (int o = 0; o < ODIM; o++) dot[o] += W2s[o * HDIM + h];
                }
            }
            #pragma unroll
            for (int o = 0; o < ODIM; o++) {
                float v = dot[o];
                v += __shfl_xor_sync(0xffffffffu, v, 16);
                v += __shfl_xor_sync(0xffffffffu, v, 8);
                v += __shfl_xor_sync(0xffffffffu, v, 4);
                v += __shfl_xor_sync(0xffffffffu, v, 2);
                v += __shfl_xor_sync(0xffffffffu, v, 1);
                if (lane == 0) {
                    float mm = DECAY_F * m2s[r * ODIM + o] + v;
                    if (mm > THRESH_F) { ss[r * ODIM + o] += 1.0f; mm = 0.0f; }
                    m2s[r * ODIM + o] = mm;
                }
            }
        }
        __syncthreads();
    }

    // ---------- output: sumspike / T ----------
    for (int i = tid; i < BM * ODIM; i += NTHREADS) {
        int r = i / ODIM, o = i % ODIM;
        out[(size_t)(rowbase + r) * ODIM + o] = ss[r * ODIM + o] * (1.0f / TSTEPS);
    }
}

// ---------------------------------------------------------------------------
extern "C" void kernel_launch(void* const* d_in, const int* in_sizes, int n_in,
                              void* d_out, int out_size) {
    const float* input  = (const float*)d_in[0];   // [8192,1,28,28]
    const float* rand_u = (const float*)d_in[1];   // [50,8192,784]
    const float* W1     = (const float*)d_in[2];   // [1024,784]
    const float* W2     = (const float*)d_in[3];   // [10,1024]
    float* out = (float*)d_out;                    // [8192,10]

    const int smem_bytes = (KB * HDIM + ODIM * HDIM) * 4      // w_tile + W2s
                         + (BM * 27 + BM * 32) * 4            // x_mask + s1_mask
                         + 2 * BM * ODIM * 4;                 // m2s + ss
    static bool attr_set = false;
    if (!attr_set) {
        cudaFuncSetAttribute(snn_kernel,
                             cudaFuncAttributeMaxDynamicSharedMemorySize, smem_bytes);
        attr_set = true;
    }

    dim3 tb(32, 8);
    dim3 tg((JDIM + 31) / 32, HDIM / 32);
    transpose_w1_kernel<<<tg, tb>>>(W1);
    snn_kernel<<<B_TOTAL / BM, NTHREADS, smem_bytes>>>(input, rand_u, W2, out);
}

// round 6
// speedup vs baseline: 2.7893x; 2.7893x over previous
#include <cuda_runtime.h>
#include <cuda_fp16.h>
#include <cstdint>

// ============================================================================
// Problem constants
// ============================================================================
#define TSTEPS   50
#define TCHUNK   10
#define NCHUNKS  (TSTEPS / TCHUNK)          // 5
#define BTOT     8192
#define JDIM     784
#define KPAD     832                        // 13 * 64
#define NKC      13                         // K chunks of 64
#define HDIM     1024
#define ODIM     10
#define THRESH_F 0.5f

// GEMM tiling: CTA = 128(M batch) x 128(N hidden), 8 warps (4M x 2N),
// warp tile 32x64, mma m16n8k16 grid per warp: 2(M) x 8(N)
#define MT 128
#define NT 128

// smem layout: [xwords 13312B][Bbuf0 18432B][Bbuf1 18432B]
#define XW_BYTES   (MT * NKC * 8)           // 13312
#define BROW_PITCH 144                      // 64 halves (128B) padded to 144B
#define BBUF_BYTES (NT * BROW_PITCH)        // 18432
#define SMEM_G     (XW_BYTES + 2 * BBUF_BYTES)   // 50176

// ============================================================================
// Static device scratch (allocation-free rule: __device__ globals)
// ============================================================================
__device__ unsigned long long g_xbits[(size_t)TSTEPS * BTOT * NKC];   // ~42.6 MB
__device__ __half g_Bhi[(size_t)HDIM * KPAD];                         // 1.7 MB
__device__ __half g_Blo[(size_t)HDIM * KPAD];                         // 1.7 MB
__device__ float  g_C[(size_t)TCHUNK * BTOT * HDIM];                  // ~335 MB
__device__ unsigned long long g_m1[(size_t)BTOT * (HDIM / 2)];        // 33.5 MB
__device__ float  g_m2[BTOT * ODIM];
__device__ float  g_ss[BTOT * ODIM];

// ============================================================================
// Kernel 1: split W1 into fp16 hi + scaled fp16 lo, pad K 784->832 with zeros
// ============================================================================
__global__ void wsplit_kernel(const float* __restrict__ W1) {
    int idx = blockIdx.x * 256 + threadIdx.x;
    if (idx >= HDIM * KPAD) return;
    int n = idx / KPAD, k = idx % KPAD;
    float w = (k < JDIM) ? W1[n * JDIM + k] : 0.0f;
    __half hi = __float2half_rn(w);
    __half lo = __float2half_rn((w - __half2float(hi)) * 2048.0f);
    g_Bhi[idx] = hi;
    g_Blo[idx] = lo;
}

// ============================================================================
// Kernel 2: pack x_t = (sample > rand_t) into 64-bit masks (13 words per row)
// ============================================================================
__global__ __launch_bounds__(256)
void xbits_kernel(const float* __restrict__ sample,
                  const float* __restrict__ rand_u) {
    const int lane = threadIdx.x & 31;
    const int wid = threadIdx.x >> 5;
    const size_t row = (size_t)blockIdx.x * 8 + wid;   // 0 .. 50*8192-1
    const int t = (int)(row / BTOT);
    const int b = (int)(row % BTOT);
    const float* s = sample + (size_t)b * JDIM;
    const float* r = rand_u + ((size_t)t * BTOT + b) * JDIM;
    unsigned long long* dst = g_xbits + row * NKC;
    #pragma unroll
    for (int w = 0; w < NKC; w++) {
        int j0 = w * 64 + lane;
        int j1 = j0 + 32;
        bool b0 = (j0 < JDIM) && (s[j0] > r[j0]);
        bool b1 = (j1 < JDIM) && (s[j1] > r[j1]);
        unsigned lo = __ballot_sync(0xffffffffu, b0);
        unsigned hi = __ballot_sync(0xffffffffu, b1);
        if (lane == 0)
            dst[w] = ((unsigned long long)hi << 32) | (unsigned long long)lo;
    }
}

// ============================================================================
// mma.sync helpers (portable HMMA — no arch-specific target needed)
// ============================================================================
__device__ __forceinline__ void mma16816(float* c, const uint32_t* a,
                                         uint32_t b0, uint32_t b1) {
    asm volatile(
        "mma.sync.aligned.m16n8k16.row.col.f32.f16.f16.f32 "
        "{%0,%1,%2,%3}, {%4,%5,%6,%7}, {%8,%9}, {%0,%1,%2,%3};"
        : "+f"(c[0]), "+f"(c[1]), "+f"(c[2]), "+f"(c[3])
        : "r"(a[0]), "r"(a[1]), "r"(a[2]), "r"(a[3]), "r"(b0), "r"(b1));
}

// 2 x-bits at (pos, pos+1) -> packed fp16 pair {0/1, 0/1}
__device__ __forceinline__ uint32_t pair_to_h2(uint32_t s, int pos) {
    uint32_t b = s >> pos;
    return ((b & 1u) * 0x3C00u) | ((b & 2u) * 0x1E000000u);
}

// ============================================================================
// Kernel 3: HMMA GEMM over one T-chunk.
//   C[tl, b, n] = x @ Whi^T + 2^-11 * (x @ Wlo^T)
//   grid (64*TCHUNK, 8), block 256.
//   Pass order: lo-GEMM -> acc *= 2^-11 -> hi-GEMM (single accumulator).
// ============================================================================
__global__ __launch_bounds__(256, 1)
void gemm_kernel(int t0) {
    extern __shared__ char smem[];
    unsigned long long* xw = (unsigned long long*)smem;     // [128][13]
    char* Bbuf[2] = { smem + XW_BYTES, smem + XW_BYTES + BBUF_BYTES };

    const int tid = threadIdx.x;
    const int lane = tid & 31;
    const int wid = tid >> 5;
    const int g = lane >> 2;            // group id 0..7
    const int t4 = lane & 3;            // thread-in-group 0..3
    const int tsh = t4 * 2;
    const int mwarp = wid & 3;          // 0..3 -> 32-row M group
    const int nwarp = wid >> 2;         // 0..1 -> 64-col N group

    const int tl = blockIdx.x >> 6;          // 0..TCHUNK-1
    const int btile = blockIdx.x & 63;       // 0..63
    const int nb = blockIdx.y;               // 0..7
    const int tglob = t0 + tl;

    // ---- stage all x-bit words for this 128-row m-tile (linear copy) ----
    {
        const unsigned long long* src =
            g_xbits + ((size_t)tglob * BTOT + (size_t)btile * MT) * NKC;
        #pragma unroll
        for (int i = 0; i < 7; i++) {
            int idx = tid + i * 256;
            if (idx < MT * NKC) xw[idx] = src[idx];
        }
    }

    float acc[2][8][4];
    #pragma unroll
    for (int mm = 0; mm < 2; mm++)
        #pragma unroll
        for (int nn = 0; nn < 8; nn++)
            #pragma unroll
            for (int q = 0; q < 4; q++) acc[mm][nn][q] = 0.0f;

    const int rb = mwarp * 32;                               // warp M base
    const int bcol_base = (nwarp * 64 + g) * BROW_PITCH + t4 * 4;

    #pragma unroll 1
    for (int pass = 0; pass < 2; pass++) {
        const __half* Bg = pass ? g_Bhi : g_Blo;
        const char* Bsrc = (const char*)(Bg + (size_t)nb * NT * KPAD);

        // stage kb=0 into buf0: 128 rows x 8 uint4
        #pragma unroll
        for (int j = 0; j < 4; j++) {
            int idx = tid + j * 256;
            int row = idx >> 3, q = idx & 7;
            uint4 v = *(const uint4*)(Bsrc + (size_t)row * (KPAD * 2) + q * 16);
            *(uint4*)(Bbuf[0] + row * BROW_PITCH + q * 16) = v;
        }
        __syncthreads();

        #pragma unroll 1
        for (int kb = 0; kb < NKC; kb++) {
            const char* Bs = Bbuf[kb & 1];

            // prefetch next chunk into the other buffer
            if (kb + 1 < NKC) {
                char* Bn = Bbuf[(kb + 1) & 1];
                const char* src = Bsrc + (kb + 1) * 128;
                #pragma unroll
                for (int j = 0; j < 4; j++) {
                    int idx = tid + j * 256;
                    int row = idx >> 3, q = idx & 7;
                    uint4 v = *(const uint4*)(src + (size_t)row * (KPAD * 2) + q * 16);
                    *(uint4*)(Bn + row * BROW_PITCH + q * 16) = v;
                }
            }

            // x words for this warp's 2 m16 subtiles (rows g, g+8, g+16, g+24)
            unsigned long long w00 = xw[(rb + g) * NKC + kb];
            unsigned long long w01 = xw[(rb + g + 8) * NKC + kb];
            unsigned long long w10 = xw[(rb + g + 16) * NKC + kb];
            unsigned long long w11 = xw[(rb + g + 24) * NKC + kb];

            #pragma unroll
            for (int ks = 0; ks < 4; ks++) {
                const uint32_t s00 = (uint32_t)(w00 >> (ks * 16));
                const uint32_t s01 = (uint32_t)(w01 >> (ks * 16));
                const uint32_t s10 = (uint32_t)(w10 >> (ks * 16));
                const uint32_t s11 = (uint32_t)(w11 >> (ks * 16));
                uint32_t a0[4], a1[4];
                a0[0] = pair_to_h2(s00, tsh);
                a0[1] = pair_to_h2(s01, tsh);
                a0[2] = pair_to_h2(s00, tsh + 8);
                a0[3] = pair_to_h2(s01, tsh + 8);
                a1[0] = pair_to_h2(s10, tsh);
                a1[1] = pair_to_h2(s11, tsh);
                a1[2] = pair_to_h2(s10, tsh + 8);
                a1[3] = pair_to_h2(s11, tsh + 8);

                const char* bp = Bs + bcol_base + ks * 32;
                #pragma unroll
                for (int nn = 0; nn < 8; nn++) {
                    uint32_t b0 = *(const uint32_t*)(bp + nn * 8 * BROW_PITCH);
                    uint32_t b1 = *(const uint32_t*)(bp + nn * 8 * BROW_PITCH + 16);
                    mma16816(acc[0][nn], a0, b0, b1);
                    mma16816(acc[1][nn], a1, b0, b1);
                }
            }
            __syncthreads();
        }

        if (pass == 0) {
            #pragma unroll
            for (int mm = 0; mm < 2; mm++)
                #pragma unroll
                for (int nn = 0; nn < 8; nn++)
                    #pragma unroll
                    for (int q = 0; q < 4; q++)
                        acc[mm][nn][q] *= (1.0f / 2048.0f);
        }
    }

    // ---- epilogue: write fp32 C ----
    // c0:(g,2t) c1:(g,2t+1) c2:(g+8,2t) c3:(g+8,2t+1)
    const size_t rowbase = (size_t)tl * BTOT + (size_t)btile * MT + rb;
    const int colbase = nb * NT + nwarp * 64 + tsh;
    #pragma unroll
    for (int mm = 0; mm < 2; mm++) {
        float* r0 = g_C + (rowbase + mm * 16 + g) * HDIM + colbase;
        float* r1 = r0 + 8 * HDIM;
        #pragma unroll
        for (int nn = 0; nn < 8; nn++) {
            float2 v0 = make_float2(acc[mm][nn][0], acc[mm][nn][1]);
            float2 v1 = make_float2(acc[mm][nn][2], acc[mm][nn][3]);
            *(float2*)(r0 + nn * 8) = v0;
            *(float2*)(r1 + nn * 8) = v1;
        }
    }
}

// Packed fp32x2 helper (scan kernel)
#define FMA_DECAY_F32X2(acc, dec2, c2) \
    asm("fma.rn.f32x2 %0, %0, %1, %2;" : "+l"(acc) : "l"(dec2), "l"(c2))

// ============================================================================
// Kernel 4: sequential membrane scan over one T-chunk.
//   CTA = 32 batch rows; m1 in 64 packed f32x2 regs/thread
// ============================================================================
__global__ __launch_bounds__(256, 1)
void scan_kernel(const float* __restrict__ W2, float* __restrict__ out, int t0) {
    __shared__ float    W2s[ODIM * HDIM];     // 40 KB
    __shared__ unsigned s1_mask[32 * 32];     // 4 KB
    __shared__ float    m2s[32 * ODIM];
    __shared__ float    ss[32 * ODIM];

    const int tid = threadIdx.x;
    const int lane = tid & 31;
    const int wid = tid >> 5;
    const int rowbase = blockIdx.x * 32;
    const int cbase = wid * 128;

    for (int i = tid; i < ODIM * HDIM; i += 256) W2s[i] = W2[i];
    if (t0 == 0) {
        for (int i = tid; i < 32 * ODIM; i += 256) { m2s[i] = 0.0f; ss[i] = 0.0f; }
    } else {
        for (int i = tid; i < 32 * ODIM; i += 256) {
            int r = i / ODIM, o = i % ODIM;
            m2s[i] = g_m2[(rowbase + r) * ODIM + o];
            ss[i]  = g_ss[(rowbase + r) * ODIM + o];
        }
    }

    unsigned long long acc[64];
    const size_t mbase = (size_t)(rowbase + lane) * (HDIM / 2) + wid * 64;
    if (t0 == 0) {
        #pragma unroll
        for (int i = 0; i < 64; i++) acc[i] = 0ull;
    } else {
        #pragma unroll
        for (int i = 0; i < 64; i++) acc[i] = g_m1[mbase + i];
    }
    const unsigned long long DEC2 = 0x3E4CCCCD3E4CCCCDull;   // (0.2f, 0.2f)
    __syncthreads();

    for (int tt = 0; tt < TCHUNK; tt++) {
        // ---- m1 = decay*m1 + C_t (streaming loads) ----
        const ulonglong2* crow = (const ulonglong2*)
            (g_C + ((size_t)tt * BTOT + rowbase + lane) * HDIM + cbase);
        #pragma unroll
        for (int p = 0; p < 32; p++) {
            ulonglong2 c2 = __ldcs(crow + p);
            FMA_DECAY_F32X2(acc[2 * p],     DEC2, c2.x);
            FMA_DECAY_F32X2(acc[2 * p + 1], DEC2, c2.y);
        }

        // ---- spike, reset-on-spike, pack s1 bitmask ----
        #pragma unroll
        for (int wd = 0; wd < 4; wd++) {
            unsigned bits = 0;
            #pragma unroll
            for (int p = 0; p < 16; p++) {
                const int pi = wd * 16 + p;
                float flo = __uint_as_float((unsigned)(acc[pi] & 0xffffffffull));
                float fhi = __uint_as_float((unsigned)(acc[pi] >> 32));
                if (flo > THRESH_F) { bits |= 1u << (2 * p);     flo = 0.0f; }
                if (fhi > THRESH_F) { bits |= 1u << (2 * p + 1); fhi = 0.0f; }
                acc[pi] = ((unsigned long long)__float_as_uint(fhi) << 32) |
                          (unsigned long long)__float_as_uint(flo);
            }
            s1_mask[lane * 32 + (wid * 4 + wd)] = bits;
        }
        __syncthreads();

        // ---- layer 2: warp per row, masked adds + shfl reduce ----
        #pragma unroll
        for (int rr = 0; rr < 4; rr++) {
            const int r = wid * 4 + rr;
            float dot[ODIM];
            #pragma unroll
            for (int o = 0; o < ODIM; o++) dot[o] = 0.0f;
            #pragma unroll 4
            for (int k = 0; k < 32; k++) {
                const unsigned wmask = s1_mask[r * 32 + k];
                if ((wmask >> lane) & 1u) {
                    const int h = k * 32 + lane;
                    #pragma unroll
                    for (int o = 0; o < ODIM; o++) dot[o] += W2s[o * HDIM + h];
                }
            }
            #pragma unroll
            for (int o = 0; o < ODIM; o++) {
                float v = dot[o];
                v += __shfl_xor_sync(0xffffffffu, v, 16);
                v += __shfl_xor_sync(0xffffffffu, v, 8);
                v += __shfl_xor_sync(0xffffffffu, v, 4);
                v += __shfl_xor_sync(0xffffffffu, v, 2);
                v += __shfl_xor_sync(0xffffffffu, v, 1);
                if (lane == 0) {
                    float mm = 0.2f * m2s[r * ODIM + o] + v;
                    if (mm > THRESH_F) { ss[r * ODIM + o] += 1.0f; mm = 0.0f; }
                    m2s[r * ODIM + o] = mm;
                }
            }
        }
        __syncthreads();
    }

    // ---- spill state; write output on the final chunk ----
    #pragma unroll
    for (int i = 0; i < 64; i++) g_m1[mbase + i] = acc[i];
    for (int i = tid; i < 32 * ODIM; i += 256) {
        int r = i / ODIM, o = i % ODIM;
        g_m2[(rowbase + r) * ODIM + o] = m2s[i];
        g_ss[(rowbase + r) * ODIM + o] = ss[i];
    }
    if (t0 + TCHUNK >= TSTEPS) {
        for (int i = tid; i < 32 * ODIM; i += 256) {
            int r = i / ODIM, o = i % ODIM;
            out[(size_t)(rowbase + r) * ODIM + o] = ss[i] * (1.0f / TSTEPS);
        }
    }
}

// ============================================================================
extern "C" void kernel_launch(void* const* d_in, const int* in_sizes, int n_in,
                              void* d_out, int out_size) {
    const float* input  = (const float*)d_in[0];   // [8192,1,28,28] == [8192,784]
    const float* rand_u = (const float*)d_in[1];   // [50,8192,784]
    const float* W1     = (const float*)d_in[2];   // [1024,784]
    const float* W2     = (const float*)d_in[3];   // [10,1024]
    float* out = (float*)d_out;                    // [8192,10]

    static bool attr_set = false;
    if (!attr_set) {
        cudaFuncSetAttribute(gemm_kernel,
                             cudaFuncAttributeMaxDynamicSharedMemorySize, SMEM_G);
        attr_set = true;
    }

    // 1) split W1 into fp16 hi/lo (K padded to 832)
    wsplit_kernel<<<(HDIM * KPAD + 255) / 256, 256>>>(W1);

    // 2) pack all x_t into bitmasks
    xbits_kernel<<<(TSTEPS * BTOT) / 8, 256>>>(input, rand_u);

    // 3) per T-chunk: HMMA GEMM then sequential scan
    for (int c = 0; c < NCHUNKS; c++) {
        const int t0 = c * TCHUNK;
        dim3 ggrid(64 * TCHUNK, HDIM / NT);   // (640, 8)
        gemm_kernel<<<ggrid, 256, SMEM_G>>>(t0);
        scan_kernel<<<BTOT / 32, 256>>>(W2, out, t0);
    }
}

// round 7
// speedup vs baseline: 4.1764x; 1.4973x over previous
#include <cuda_runtime.h>
#include <cuda_fp16.h>
#include <cstdint>

// ============================================================================
// Problem constants
// ============================================================================
#define TSTEPS   50
#define TCHUNK   10
#define NCHUNKS  (TSTEPS / TCHUNK)          // 5
#define BTOT     8192
#define JDIM     784
#define KPAD     832                        // 13 * 64
#define NKC      13                         // K chunks of 64
#define HDIM     1024
#define ODIM     10
#define THRESH_F 0.5f

// GEMM tiling: CTA = 128(M) x 128(N), 8 warps (4M x 2N), warp tile 32x64
#define MT 128
#define NT 128

// smem layout: [xw 13312][A0 18432][A1 18432][B0 18432][B1 18432]
#define PITCH      144                      // 64 halves (128B) padded to 144B
#define TILE_BYTES (128 * PITCH)            // 18432
#define XW_BYTES   (MT * NKC * 8)           // 13312
#define OFF_A0     XW_BYTES
#define OFF_A1     (XW_BYTES + TILE_BYTES)
#define OFF_B0     (XW_BYTES + 2 * TILE_BYTES)
#define OFF_B1     (XW_BYTES + 3 * TILE_BYTES)
#define SMEM_G     (XW_BYTES + 4 * TILE_BYTES)   // 87040

// ============================================================================
// Static device scratch (allocation-free rule: __device__ globals)
// ============================================================================
__device__ unsigned long long g_xbits[(size_t)TSTEPS * BTOT * NKC];   // ~42.6 MB
__device__ __half g_Bhi[(size_t)HDIM * KPAD];                         // 1.7 MB
__device__ __half g_Blo[(size_t)HDIM * KPAD];                         // 1.7 MB
__device__ float  g_C[(size_t)TCHUNK * BTOT * HDIM];                  // ~335 MB
__device__ unsigned long long g_m1[(size_t)BTOT * (HDIM / 2)];        // 33.5 MB
__device__ float  g_m2[BTOT * ODIM];
__device__ float  g_ss[BTOT * ODIM];

// ============================================================================
// Kernel 1: split W1 into fp16 hi + scaled fp16 lo, pad K 784->832 with zeros
// ============================================================================
__global__ void wsplit_kernel(const float* __restrict__ W1) {
    int idx = blockIdx.x * 256 + threadIdx.x;
    if (idx >= HDIM * KPAD) return;
    int n = idx / KPAD, k = idx % KPAD;
    float w = (k < JDIM) ? W1[n * JDIM + k] : 0.0f;
    __half hi = __float2half_rn(w);
    __half lo = __float2half_rn((w - __half2float(hi)) * 2048.0f);
    g_Bhi[idx] = hi;
    g_Blo[idx] = lo;
}

// ============================================================================
// Kernel 2: pack x_t = (sample > rand_t) into 64-bit masks (13 words per row)
// ============================================================================
__global__ __launch_bounds__(256)
void xbits_kernel(const float* __restrict__ sample,
                  const float* __restrict__ rand_u) {
    const int lane = threadIdx.x & 31;
    const int wid = threadIdx.x >> 5;
    const size_t row = (size_t)blockIdx.x * 8 + wid;   // 0 .. 50*8192-1
    const int t = (int)(row / BTOT);
    const int b = (int)(row % BTOT);
    const float* s = sample + (size_t)b * JDIM;
    const float* r = rand_u + ((size_t)t * BTOT + b) * JDIM;
    unsigned long long* dst = g_xbits + row * NKC;
    #pragma unroll
    for (int w = 0; w < NKC; w++) {
        int j0 = w * 64 + lane;
        int j1 = j0 + 32;
        bool b0 = (j0 < JDIM) && (s[j0] > r[j0]);
        bool b1 = (j1 < JDIM) && (s[j1] > r[j1]);
        unsigned lo = __ballot_sync(0xffffffffu, b0);
        unsigned hi = __ballot_sync(0xffffffffu, b1);
        if (lane == 0)
            dst[w] = ((unsigned long long)hi << 32) | (unsigned long long)lo;
    }
}

// ============================================================================
// MMA / ldmatrix helpers (portable PTX — no arch-specific target)
// ============================================================================
__device__ __forceinline__ void mma16816(float* c, const uint32_t* a,
                                         uint32_t b0, uint32_t b1) {
    asm volatile(
        "mma.sync.aligned.m16n8k16.row.col.f32.f16.f16.f32 "
        "{%0,%1,%2,%3}, {%4,%5,%6,%7}, {%8,%9}, {%0,%1,%2,%3};"
        : "+f"(c[0]), "+f"(c[1]), "+f"(c[2]), "+f"(c[3])
        : "r"(a[0]), "r"(a[1]), "r"(a[2]), "r"(a[3]), "r"(b0), "r"(b1));
}

#define LDSM_X4(r0, r1, r2, r3, addr) \
    asm volatile("ldmatrix.sync.aligned.m8n8.x4.shared.b16 {%0,%1,%2,%3}, [%4];" \
                 : "=r"(r0), "=r"(r1), "=r"(r2), "=r"(r3) : "r"(addr))

__device__ __forceinline__ uint32_t smem_u32(const void* p) {
    uint32_t a;
    asm("{ .reg .u64 t; cvta.to.shared.u64 t, %1; cvt.u32.u64 %0, t; }"
        : "=r"(a) : "l"(p));
    return a;
}

// 2 x-bits at (pos, pos+1) -> packed fp16 pair {0/1, 0/1}
__device__ __forceinline__ uint32_t pair_to_h2(uint32_t s, int pos) {
    uint32_t b = s >> pos;
    return ((b & 1u) * 0x3C00u) | ((b & 2u) * 0x1E000000u);
}

// ============================================================================
// Kernel 3: HMMA GEMM over one T-chunk (ldmatrix + smem-decoded A).
//   C[tl, b, n] = x @ Whi^T + 2^-11 * (x @ Wlo^T)
//   grid (64*TCHUNK, 8), block 256. Pass order: lo -> acc*=2^-11 -> hi.
// ============================================================================
__global__ __launch_bounds__(256)
void gemm_kernel(int t0) {
    extern __shared__ char smem[];
    unsigned long long* xw = (unsigned long long*)smem;     // [128][13]
    const uint32_t sbase = smem_u32(smem);

    const int tid = threadIdx.x;
    const int lane = tid & 31;
    const int wid = tid >> 5;
    const int g = lane >> 2;            // 0..7
    const int t4 = lane & 3;            // 0..3
    const int tsh = t4 * 2;
    const int mwarp = wid & 3;          // 0..3 -> 32-row M group
    const int nwarp = wid >> 2;         // 0..1 -> 64-col N group

    const int tl = blockIdx.x >> 6;          // 0..TCHUNK-1
    const int btile = blockIdx.x & 63;       // 0..63
    const int nb = blockIdx.y;               // 0..7
    const int tglob = t0 + tl;

    // decode thread mapping: row = tid>>1, half-word = tid&1
    const int drow = tid >> 1;
    const int dh = tid & 1;

    // ldmatrix per-lane row/byte offsets
    const uint32_t a_off = (uint32_t)((lane & 15) * PITCH + (lane >> 4) * 16);
    const uint32_t b_off = (uint32_t)
        (((lane & 7) + ((lane >> 4) << 3)) * PITCH + (((lane >> 3) & 1) << 4));

    // ---- stage all x-bit words for this 128-row m-tile ----
    {
        const unsigned long long* src =
            g_xbits + ((size_t)tglob * BTOT + (size_t)btile * MT) * NKC;
        #pragma unroll
        for (int i = 0; i < 7; i++) {
            int idx = tid + i * 256;
            if (idx < MT * NKC) xw[idx] = src[idx];
        }
    }
    __syncthreads();

    float acc[2][8][4];
    #pragma unroll
    for (int mm = 0; mm < 2; mm++)
        #pragma unroll
        for (int nn = 0; nn < 8; nn++)
            #pragma unroll
            for (int q = 0; q < 4; q++) acc[mm][nn][q] = 0.0f;

    #pragma unroll 1
    for (int pass = 0; pass < 2; pass++) {
        const char* Bg = (const char*)((pass ? g_Bhi : g_Blo) + (size_t)nb * NT * KPAD);

        // ---- prologue: stage kb=0 into buffer 0 ----
        {
            // decode A
            uint32_t bits = (uint32_t)(xw[drow * NKC + 0] >> (dh << 5));
            uint4* adst = (uint4*)(smem + OFF_A0 + drow * PITCH + dh * 64);
            #pragma unroll
            for (int q = 0; q < 4; q++) {
                uint4 v;
                v.x = pair_to_h2(bits, q * 8 + 0);
                v.y = pair_to_h2(bits, q * 8 + 2);
                v.z = pair_to_h2(bits, q * 8 + 4);
                v.w = pair_to_h2(bits, q * 8 + 6);
                adst[q] = v;
            }
            // copy B
            #pragma unroll
            for (int j = 0; j < 4; j++) {
                int idx = tid + j * 256;
                int r = idx >> 3, q = idx & 7;
                uint4 v = *(const uint4*)(Bg + (size_t)r * (KPAD * 2) + q * 16);
                *(uint4*)(smem + OFF_B0 + r * PITCH + q * 16) = v;
            }
        }
        __syncthreads();

        #pragma unroll 1
        for (int kb = 0; kb < NKC; kb++) {
            const int buf = kb & 1;

            // ---- stage kb+1 into the other buffer ----
            if (kb + 1 < NKC) {
                const int aoff = (buf ? OFF_A0 : OFF_A1);
                const int boff = (buf ? OFF_B0 : OFF_B1);
                uint32_t bits = (uint32_t)(xw[drow * NKC + kb + 1] >> (dh << 5));
                uint4* adst = (uint4*)(smem + aoff + drow * PITCH + dh * 64);
                #pragma unroll
                for (int q = 0; q < 4; q++) {
                    uint4 v;
                    v.x = pair_to_h2(bits, q * 8 + 0);
                    v.y = pair_to_h2(bits, q * 8 + 2);
                    v.z = pair_to_h2(bits, q * 8 + 4);
                    v.w = pair_to_h2(bits, q * 8 + 6);
                    adst[q] = v;
                }
                const char* src = Bg + (kb + 1) * 128;
                #pragma unroll
                for (int j = 0; j < 4; j++) {
                    int idx = tid + j * 256;
                    int r = idx >> 3, q = idx & 7;
                    uint4 v = *(const uint4*)(src + (size_t)r * (KPAD * 2) + q * 16);
                    *(uint4*)(smem + boff + r * PITCH + q * 16) = v;
                }
            }

            // ---- MMAs on current buffer ----
            const uint32_t Ab = sbase + (buf ? OFF_A1 : OFF_A0);
            const uint32_t Bb = sbase + (buf ? OFF_B1 : OFF_B0);
            const uint32_t a0_addr = Ab + (uint32_t)(mwarp * 32) * PITCH + a_off;
            const uint32_t a1_addr = a0_addr + 16 * PITCH;
            const uint32_t bb_addr = Bb + (uint32_t)(nwarp * 64) * PITCH + b_off;

            #pragma unroll
            for (int ks = 0; ks < 4; ks++) {
                uint32_t A0[4], A1[4];
                LDSM_X4(A0[0], A0[1], A0[2], A0[3], a0_addr + ks * 32);
                LDSM_X4(A1[0], A1[1], A1[2], A1[3], a1_addr + ks * 32);
                #pragma unroll
                for (int np = 0; np < 4; np++) {
                    uint32_t B0, B1, B2, B3;
                    LDSM_X4(B0, B1, B2, B3,
                            bb_addr + (uint32_t)(np * 16) * PITCH + ks * 32);
                    mma16816(acc[0][np * 2],     A0, B0, B1);
                    mma16816(acc[1][np * 2],     A1, B0, B1);
                    mma16816(acc[0][np * 2 + 1], A0, B2, B3);
                    mma16816(acc[1][np * 2 + 1], A1, B2, B3);
                }
            }
            __syncthreads();
        }

        if (pass == 0) {
            #pragma unroll
            for (int mm = 0; mm < 2; mm++)
                #pragma unroll
                for (int nn = 0; nn < 8; nn++)
                    #pragma unroll
                    for (int q = 0; q < 4; q++)
                        acc[mm][nn][q] *= (1.0f / 2048.0f);
        }
    }

    // ---- epilogue: write fp32 C ----
    const size_t rowbase = (size_t)tl * BTOT + (size_t)btile * MT + mwarp * 32;
    const int colbase = nb * NT + nwarp * 64 + tsh;
    #pragma unroll
    for (int mm = 0; mm < 2; mm++) {
        float* r0 = g_C + (rowbase + mm * 16 + g) * HDIM + colbase;
        float* r1 = r0 + 8 * HDIM;
        #pragma unroll
        for (int nn = 0; nn < 8; nn++) {
            *(float2*)(r0 + nn * 8) = make_float2(acc[mm][nn][0], acc[mm][nn][1]);
            *(float2*)(r1 + nn * 8) = make_float2(acc[mm][nn][2], acc[mm][nn][3]);
        }
    }
}

// Packed fp32x2 helper (scan kernel)
#define FMA_DECAY_F32X2(acc, dec2, c2) \
    asm("fma.rn.f32x2 %0, %0, %1, %2;" : "+l"(acc) : "l"(dec2), "l"(c2))

// ============================================================================
// Kernel 4: sequential membrane scan over one T-chunk.
//   CTA = 16 batch rows (512 CTAs, 2 CTAs/SM); m1 in 32 packed f32x2 regs.
//   Thread: row = lane&15, 64-col slice = [wid*128 + (lane>>4)*64, +64)
// ============================================================================
#define BM2 16
__global__ __launch_bounds__(256, 2)
void scan_kernel(const float* __restrict__ W2, float* __restrict__ out, int t0) {
    __shared__ float    W2s[ODIM * HDIM];     // 40 KB
    __shared__ unsigned s1m[BM2 * 32];        // 2 KB
    __shared__ float    m2s[BM2 * ODIM];
    __shared__ float    ss[BM2 * ODIM];

    const int tid = threadIdx.x;
    const int lane = tid & 31;
    const int wid = tid >> 5;
    const int row = lane & 15;
    const int hf = lane >> 4;
    const int rowbase = blockIdx.x * BM2;
    const int colbase = wid * 128 + hf * 64;

    for (int i = tid; i < ODIM * HDIM; i += 256) W2s[i] = W2[i];
    if (t0 == 0) {
        for (int i = tid; i < BM2 * ODIM; i += 256) { m2s[i] = 0.0f; ss[i] = 0.0f; }
    } else {
        for (int i = tid; i < BM2 * ODIM; i += 256) {
            int r = i / ODIM, o = i % ODIM;
            m2s[i] = g_m2[(rowbase + r) * ODIM + o];
            ss[i]  = g_ss[(rowbase + r) * ODIM + o];
        }
    }

    unsigned long long acc[32];
    const size_t mbase = (size_t)(rowbase + row) * (HDIM / 2) + wid * 64 + hf * 32;
    if (t0 == 0) {
        #pragma unroll
        for (int i = 0; i < 32; i++) acc[i] = 0ull;
    } else {
        #pragma unroll
        for (int i = 0; i < 32; i++) acc[i] = g_m1[mbase + i];
    }
    const unsigned long long DEC2 = 0x3E4CCCCD3E4CCCCDull;   // (0.2f, 0.2f)
    __syncthreads();

    for (int tt = 0; tt < TCHUNK; tt++) {
        // ---- m1 = decay*m1 + C_t (streaming loads) ----
        const ulonglong2* crow = (const ulonglong2*)
            (g_C + ((size_t)tt * BTOT + rowbase + row) * HDIM + colbase);
        #pragma unroll
        for (int p = 0; p < 16; p++) {
            ulonglong2 c2 = __ldcs(crow + p);
            FMA_DECAY_F32X2(acc[2 * p],     DEC2, c2.x);
            FMA_DECAY_F32X2(acc[2 * p + 1], DEC2, c2.y);
        }

        // ---- spike, reset-on-spike, pack s1 bitmask (2 words/thread) ----
        #pragma unroll
        for (int wd = 0; wd < 2; wd++) {
            unsigned bits = 0;
            #pragma unroll
            for (int p = 0; p < 16; p++) {
                const int pi = wd * 16 + p;
                float flo = __uint_as_float((unsigned)(acc[pi] & 0xffffffffull));
                float fhi = __uint_as_float((unsigned)(acc[pi] >> 32));
                if (flo > THRESH_F) { bits |= 1u << (2 * p);     flo = 0.0f; }
                if (fhi > THRESH_F) { bits |= 1u << (2 * p + 1); fhi = 0.0f; }
                acc[pi] = ((unsigned long long)__float_as_uint(fhi) << 32) |
                          (unsigned long long)__float_as_uint(flo);
            }
            s1m[row * 32 + (wid * 4 + hf * 2 + wd)] = bits;
        }
        __syncthreads();

        // ---- layer 2: warp handles 2 rows, masked adds + shfl reduce ----
        #pragma unroll
        for (int rr = 0; rr < 2; rr++) {
            const int r = wid * 2 + rr;
            float dot[ODIM];
            #pragma unroll
            for (int o = 0; o < ODIM; o++) dot[o] = 0.0f;
            #pragma unroll 4
            for (int k = 0; k < 32; k++) {
                const unsigned wmask = s1m[r * 32 + k];
                if ((wmask >> lane) & 1u) {
                    const int h = k * 32 + lane;
                    #pragma unroll
                    for (int o = 0; o < ODIM; o++) dot[o] += W2s[o * HDIM + h];
                }
            }
            #pragma unroll
            for (int o = 0; o < ODIM; o++) {
                float v = dot[o];
                v += __shfl_xor_sync(0xffffffffu, v, 16);
                v += __shfl_xor_sync(0xffffffffu, v, 8);
                v += __shfl_xor_sync(0xffffffffu, v, 4);
                v += __shfl_xor_sync(0xffffffffu, v, 2);
                v += __shfl_xor_sync(0xffffffffu, v, 1);
                if (lane == 0) {
                    float mm = 0.2f * m2s[r * ODIM + o] + v;
                    if (mm > THRESH_F) { ss[r * ODIM + o] += 1.0f; mm = 0.0f; }
                    m2s[r * ODIM + o] = mm;
                }
            }
        }
        __syncthreads();
    }

    // ---- spill state; write output on the final chunk ----
    #pragma unroll
    for (int i = 0; i < 32; i++) g_m1[mbase + i] = acc[i];
    for (int i = tid; i < BM2 * ODIM; i += 256) {
        int r = i / ODIM, o = i % ODIM;
        g_m2[(rowbase + r) * ODIM + o] = m2s[i];
        g_ss[(rowbase + r) * ODIM + o] = ss[i];
    }
    if (t0 + TCHUNK >= TSTEPS) {
        for (int i = tid; i < BM2 * ODIM; i += 256) {
            int r = i / ODIM, o = i % ODIM;
            out[(size_t)(rowbase + r) * ODIM + o] = ss[i] * (1.0f / TSTEPS);
        }
    }
}

// ============================================================================
extern "C" void kernel_launch(void* const* d_in, const int* in_sizes, int n_in,
                              void* d_out, int out_size) {
    const float* input  = (const float*)d_in[0];   // [8192,1,28,28] == [8192,784]
    const float* rand_u = (const float*)d_in[1];   // [50,8192,784]
    const float* W1     = (const float*)d_in[2];   // [1024,784]
    const float* W2     = (const float*)d_in[3];   // [10,1024]
    float* out = (float*)d_out;                    // [8192,10]

    static bool attr_set = false;
    if (!attr_set) {
        cudaFuncSetAttribute(gemm_kernel,
                             cudaFuncAttributeMaxDynamicSharedMemorySize, SMEM_G);
        attr_set = true;
    }

    // 1) split W1 into fp16 hi/lo (K padded to 832)
    wsplit_kernel<<<(HDIM * KPAD + 255) / 256, 256>>>(W1);

    // 2) pack all x_t into bitmasks
    xbits_kernel<<<(TSTEPS * BTOT) / 8, 256>>>(input, rand_u);

    // 3) per T-chunk: HMMA GEMM then sequential scan
    for (int c = 0; c < NCHUNKS; c++) {
        const int t0 = c * TCHUNK;
        dim3 ggrid(64 * TCHUNK, HDIM / NT);   // (640, 8)
        gemm_kernel<<<ggrid, 256, SMEM_G>>>(t0);
        scan_kernel<<<BTOT / BM2, 256>>>(W2, out, t0);
    }
}

// round 9
// speedup vs baseline: 4.5549x; 1.0906x over previous
#include <cuda_runtime.h>
#include <cuda_fp16.h>
#include <cstdint>

// ============================================================================
// Problem constants
// ============================================================================
#define TSTEPS   50
#define TCHUNK   25
#define NCHUNKS  (TSTEPS / TCHUNK)          // 2
#define BTOT     8192
#define JDIM     784
#define KPAD     832                        // 13 * 64
#define NKC      13                         // K chunks of 64
#define HDIM     1024
#define ODIM     10
#define THRESH_F 0.5f

// GEMM tiling: CTA = 256(M) x 128(N), 16 warps (8M x 2N), warp tile 32x64
#define MT 256
#define NT 128
#define GT 512                              // gemm threads

// smem layout: [xw][A0][A1][B0][B1]
#define PITCH      144                      // 64 halves (128B) padded to 144B
#define ATILE      (MT * PITCH)             // 36864
#define BTILE      (NT * PITCH)             // 18432
#define XW_BYTES   (MT * NKC * 8)           // 26624
#define OFF_A0     XW_BYTES
#define OFF_A1     (XW_BYTES + ATILE)
#define OFF_B0     (XW_BYTES + 2 * ATILE)
#define OFF_B1     (XW_BYTES + 2 * ATILE + BTILE)
#define SMEM_G     (XW_BYTES + 2 * ATILE + 2 * BTILE)   // 137216

// ============================================================================
// Static device scratch (allocation-free rule: __device__ globals)
// ============================================================================
__device__ unsigned long long g_xbits[(size_t)TSTEPS * BTOT * NKC];   // ~42.6 MB
__device__ __half g_Bhi[(size_t)HDIM * KPAD];                         // 1.7 MB
__device__ __half g_Blo[(size_t)HDIM * KPAD];                         // 1.7 MB
__device__ float  g_C[(size_t)TCHUNK * BTOT * HDIM];                  // ~839 MB
__device__ unsigned long long g_m1[(size_t)BTOT * (HDIM / 2)];        // 33.5 MB
__device__ float  g_m2[BTOT * ODIM];
__device__ float  g_ss[BTOT * ODIM];

// ============================================================================
// Kernel 1: split W1 into fp16 hi + scaled fp16 lo, pad K 784->832 with zeros
// ============================================================================
__global__ void wsplit_kernel(const float* __restrict__ W1) {
    int idx = blockIdx.x * 256 + threadIdx.x;
    if (idx >= HDIM * KPAD) return;
    int n = idx / KPAD, k = idx % KPAD;
    float w = (k < JDIM) ? W1[n * JDIM + k] : 0.0f;
    __half hi = __float2half_rn(w);
    __half lo = __float2half_rn((w - __half2float(hi)) * 2048.0f);
    g_Bhi[idx] = hi;
    g_Blo[idx] = lo;
}

// ============================================================================
// Kernel 2: pack x_t = (sample > rand_t) into 64-bit masks (13 words per row)
// ============================================================================
__global__ __launch_bounds__(256)
void xbits_kernel(const float* __restrict__ sample,
                  const float* __restrict__ rand_u) {
    const int lane = threadIdx.x & 31;
    const int wid = threadIdx.x >> 5;
    const size_t row = (size_t)blockIdx.x * 8 + wid;   // 0 .. 50*8192-1
    const int t = (int)(row / BTOT);
    const int b = (int)(row % BTOT);
    const float* s = sample + (size_t)b * JDIM;
    const float* r = rand_u + ((size_t)t * BTOT + b) * JDIM;
    unsigned long long* dst = g_xbits + row * NKC;
    #pragma unroll
    for (int w = 0; w < NKC; w++) {
        int j0 = w * 64 + lane;
        int j1 = j0 + 32;
        bool b0 = (j0 < JDIM) && (s[j0] > r[j0]);
        bool b1 = (j1 < JDIM) && (s[j1] > r[j1]);
        unsigned lo = __ballot_sync(0xffffffffu, b0);
        unsigned hi = __ballot_sync(0xffffffffu, b1);
        if (lane == 0)
            dst[w] = ((unsigned long long)hi << 32) | (unsigned long long)lo;
    }
}

// ============================================================================
// MMA / ldmatrix helpers (portable PTX — no arch-specific target)
// ============================================================================
__device__ __forceinline__ void mma16816(float* c, const uint32_t* a,
                                         uint32_t b0, uint32_t b1) {
    asm volatile(
        "mma.sync.aligned.m16n8k16.row.col.f32.f16.f16.f32 "
        "{%0,%1,%2,%3}, {%4,%5,%6,%7}, {%8,%9}, {%0,%1,%2,%3};"
        : "+f"(c[0]), "+f"(c[1]), "+f"(c[2]), "+f"(c[3])
        : "r"(a[0]), "r"(a[1]), "r"(a[2]), "r"(a[3]), "r"(b0), "r"(b1));
}

#define LDSM_X4(r0, r1, r2, r3, addr) \
    asm volatile("ldmatrix.sync.aligned.m8n8.x4.shared.b16 {%0,%1,%2,%3}, [%4];" \
                 : "=r"(r0), "=r"(r1), "=r"(r2), "=r"(r3) : "r"(addr))

__device__ __forceinline__ uint32_t smem_u32(const void* p) {
    uint32_t a;
    asm("{ .reg .u64 t; cvta.to.shared.u64 t, %1; cvt.u32.u64 %0, t; }"
        : "=r"(a) : "l"(p));
    return a;
}

// 2 x-bits at (pos, pos+1) -> packed fp16 pair {0/1, 0/1}
__device__ __forceinline__ uint32_t pair_to_h2(uint32_t s, int pos) {
    uint32_t b = s >> pos;
    return ((b & 1u) * 0x3C00u) | ((b & 2u) * 0x1E000000u);
}

// ============================================================================
// Kernel 3: HMMA GEMM over one T-chunk (ldmatrix + smem-decoded A).
//   C[tl, b, n] = x @ Whi^T + 2^-11 * (x @ Wlo^T)
//   grid (32*TCHUNK, 8), block 512. Pass order: lo -> acc*=2^-11 -> hi.
// ============================================================================
__global__ __launch_bounds__(GT)
void gemm_kernel(int t0) {
    extern __shared__ char smem[];
    unsigned long long* xw = (unsigned long long*)smem;     // [256][13]
    const uint32_t sbase = smem_u32(smem);

    const int tid = threadIdx.x;
    const int lane = tid & 31;
    const int wid = tid >> 5;           // 0..15
    const int g = lane >> 2;            // 0..7
    const int t4 = lane & 3;            // 0..3
    const int tsh = t4 * 2;
    const int mwarp = wid & 7;          // 0..7 -> 32-row M group
    const int nwarp = wid >> 3;         // 0..1 -> 64-col N group

    const int tl = blockIdx.x >> 5;          // 0..TCHUNK-1
    const int btile = blockIdx.x & 31;       // 0..31
    const int nb = blockIdx.y;               // 0..7
    const int tglob = t0 + tl;

    // decode thread mapping: row = tid>>1, half-word = tid&1
    const int drow = tid >> 1;
    const int dh = tid & 1;

    // ldmatrix per-lane row/byte offsets
    const uint32_t a_off = (uint32_t)((lane & 15) * PITCH + (lane >> 4) * 16);
    const uint32_t b_off = (uint32_t)
        (((lane & 7) + ((lane >> 4) << 3)) * PITCH + (((lane >> 3) & 1) << 4));

    // ---- stage all x-bit words for this 256-row m-tile ----
    {
        const unsigned long long* src =
            g_xbits + ((size_t)tglob * BTOT + (size_t)btile * MT) * NKC;
        #pragma unroll
        for (int i = 0; i < 7; i++) {
            int idx = tid + i * GT;
            if (idx < MT * NKC) xw[idx] = src[idx];
        }
    }
    __syncthreads();

    float acc[2][8][4];
    #pragma unroll
    for (int mm = 0; mm < 2; mm++)
        #pragma unroll
        for (int nn = 0; nn < 8; nn++)
            #pragma unroll
            for (int q = 0; q < 4; q++) acc[mm][nn][q] = 0.0f;

    #pragma unroll 1
    for (int pass = 0; pass < 2; pass++) {
        const char* Bg = (const char*)((pass ? g_Bhi : g_Blo) + (size_t)nb * NT * KPAD);

        // ---- prologue: stage kb=0 into buffer 0 ----
        {
            uint32_t bits = (uint32_t)(xw[drow * NKC + 0] >> (dh << 5));
            uint4* adst = (uint4*)(smem + OFF_A0 + drow * PITCH + dh * 64);
            #pragma unroll
            for (int q = 0; q < 4; q++) {
                uint4 v;
                v.x = pair_to_h2(bits, q * 8 + 0);
                v.y = pair_to_h2(bits, q * 8 + 2);
                v.z = pair_to_h2(bits, q * 8 + 4);
                v.w = pair_to_h2(bits, q * 8 + 6);
                adst[q] = v;
            }
            #pragma unroll
            for (int j = 0; j < 2; j++) {
                int idx = tid + j * GT;
                int r = idx >> 3, q = idx & 7;
                uint4 v = *(const uint4*)(Bg + (size_t)r * (KPAD * 2) + q * 16);
                *(uint4*)(smem + OFF_B0 + r * PITCH + q * 16) = v;
            }
        }
        __syncthreads();

        #pragma unroll 1
        for (int kb = 0; kb < NKC; kb++) {
            const int buf = kb & 1;

            // ---- stage kb+1 into the other buffer ----
            if (kb + 1 < NKC) {
                const int aoff = (buf ? OFF_A0 : OFF_A1);
                const int boff = (buf ? OFF_B0 : OFF_B1);
                uint32_t bits = (uint32_t)(xw[drow * NKC + kb + 1] >> (dh << 5));
                uint4* adst = (uint4*)(smem + aoff + drow * PITCH + dh * 64);
                #pragma unroll
                for (int q = 0; q < 4; q++) {
                    uint4 v;
                    v.x = pair_to_h2(bits, q * 8 + 0);
                    v.y = pair_to_h2(bits, q * 8 + 2);
                    v.z = pair_to_h2(bits, q * 8 + 4);
                    v.w = pair_to_h2(bits, q * 8 + 6);
                    adst[q] = v;
                }
                const char* src = Bg + (kb + 1) * 128;
                #pragma unroll
                for (int j = 0; j < 2; j++) {
                    int idx = tid + j * GT;
                    int r = idx >> 3, q = idx & 7;
                    uint4 v = *(const uint4*)(src + (size_t)r * (KPAD * 2) + q * 16);
                    *(uint4*)(smem + boff + r * PITCH + q * 16) = v;
                }
            }

            // ---- MMAs on current buffer ----
            const uint32_t Ab = sbase + (buf ? OFF_A1 : OFF_A0);
            const uint32_t Bb = sbase + (buf ? OFF_B1 : OFF_B0);
            const uint32_t a0_addr = Ab + (uint32_t)(mwarp * 32) * PITCH + a_off;
            const uint32_t a1_addr = a0_addr + 16 * PITCH;
            const uint32_t bb_addr = Bb + (uint32_t)(nwarp * 64) * PITCH + b_off;

            #pragma unroll
            for (int ks = 0; ks < 4; ks++) {
                uint32_t A0[4], A1[4];
                LDSM_X4(A0[0], A0[1], A0[2], A0[3], a0_addr + ks * 32);
                LDSM_X4(A1[0], A1[1], A1[2], A1[3], a1_addr + ks * 32);
                #pragma unroll
                for (int np = 0; np < 4; np++) {
                    uint32_t B0, B1, B2, B3;
                    LDSM_X4(B0, B1, B2, B3,
                            bb_addr + (uint32_t)(np * 16) * PITCH + ks * 32);
                    mma16816(acc[0][np * 2],     A0, B0, B1);
                    mma16816(acc[1][np * 2],     A1, B0, B1);
                    mma16816(acc[0][np * 2 + 1], A0, B2, B3);
                    mma16816(acc[1][np * 2 + 1], A1, B2, B3);
                }
            }
            __syncthreads();
        }

        if (pass == 0) {
            #pragma unroll
            for (int mm = 0; mm < 2; mm++)
                #pragma unroll
                for (int nn = 0; nn < 8; nn++)
                    #pragma unroll
                    for (int q = 0; q < 4; q++)
                        acc[mm][nn][q] *= (1.0f / 2048.0f);
        }
    }

    // ---- epilogue: write fp32 C ----
    const size_t rowbase = (size_t)tl * BTOT + (size_t)btile * MT + mwarp * 32;
    const int colbase = nb * NT + nwarp * 64 + tsh;
    #pragma unroll
    for (int mm = 0; mm < 2; mm++) {
        float* r0 = g_C + (rowbase + mm * 16 + g) * HDIM + colbase;
        float* r1 = r0 + 8 * HDIM;
        #pragma unroll
        for (int nn = 0; nn < 8; nn++) {
            *(float2*)(r0 + nn * 8) = make_float2(acc[mm][nn][0], acc[mm][nn][1]);
            *(float2*)(r1 + nn * 8) = make_float2(acc[mm][nn][2], acc[mm][nn][3]);
        }
    }
}

// Packed fp32x2 helpers (scan kernel)
#define FMA_DECAY_F32X2(acc, dec2, c2) \
    asm("fma.rn.f32x2 %0, %0, %1, %2;" : "+l"(acc) : "l"(dec2), "l"(c2))
#define PACK64(lo32, hi32, dst) \
    asm("mov.b64 %0, {%1, %2};" : "=l"(dst) : "r"(lo32), "r"(hi32))

// ============================================================================
// Kernel 4: sequential membrane scan over one T-chunk.
//   CTA = 8 batch rows, 8 warps; WARP OWNS ITS ROW end-to-end:
//   - no __syncthreads in the time loop
//   - s1 bits broadcast via shfl, m2/ss live in registers (all lanes)
//   - C loads double-buffered (prefetch t+1 while processing t)
//   Thread: row = wid, cols [lane*32, lane*32+32) as 16 packed f32x2.
// ============================================================================
#define BM2 8
__global__ __launch_bounds__(256, 2)
void scan_kernel(const float* __restrict__ W2, float* __restrict__ out, int t0) {
    __shared__ float W2s[ODIM * HDIM];        // 40 KB

    const int tid = threadIdx.x;
    const int lane = tid & 31;
    const int row = tid >> 5;                 // warp id == batch row in tile
    const int rowbase = blockIdx.x * BM2;

    for (int i = tid; i < ODIM * HDIM; i += 256) W2s[i] = W2[i];

    // ---- state ----
    unsigned long long acc[16];
    float m2r[ODIM], ssr[ODIM];
    const size_t mbase = (size_t)(rowbase + row) * (HDIM / 2) + lane * 16;
    if (t0 == 0) {
        #pragma unroll
        for (int i = 0; i < 16; i++) acc[i] = 0ull;
        #pragma unroll
        for (int o = 0; o < ODIM; o++) { m2r[o] = 0.0f; ssr[o] = 0.0f; }
    } else {
        #pragma unroll
        for (int i = 0; i < 16; i++) acc[i] = g_m1[mbase + i];
        #pragma unroll
        for (int o = 0; o < ODIM; o++) {
            m2r[o] = g_m2[(rowbase + row) * ODIM + o];
            ssr[o] = g_ss[(rowbase + row) * ODIM + o];
        }
    }
    const unsigned long long DEC2 = 0x3E4CCCCD3E4CCCCDull;   // (0.2f, 0.2f)
    __syncthreads();   // W2s ready

    const size_t rowoff = (size_t)(rowbase + row) * HDIM + lane * 32;

    uint4 bufA[8], bufB[8];
    {   // prime: load C_{t0}
        const uint4* p = (const uint4*)(g_C + rowoff);
        #pragma unroll
        for (int q = 0; q < 8; q++) bufA[q] = __ldcs(p + q);
    }

    #pragma unroll 1
    for (int tt = 0; tt < TCHUNK; tt++) {
        // prefetch next step's C row into the idle buffer
        uint4* cur = (tt & 1) ? bufB : bufA;
        uint4* nxt = (tt & 1) ? bufA : bufB;
        if (tt + 1 < TCHUNK) {
            const uint4* p = (const uint4*)
                (g_C + (size_t)(tt + 1) * BTOT * HDIM + rowoff);
            #pragma unroll
            for (int q = 0; q < 8; q++) nxt[q] = __ldcs(p + q);
        }

        // ---- m1 = decay*m1 + C_t; spike; reset; pack 32 bits ----
        unsigned word = 0;
        #pragma unroll
        for (int q = 0; q < 8; q++) {
            unsigned long long c0, c1;
            PACK64(cur[q].x, cur[q].y, c0);
            PACK64(cur[q].z, cur[q].w, c1);
            FMA_DECAY_F32X2(acc[2 * q],     DEC2, c0);
            FMA_DECAY_F32X2(acc[2 * q + 1], DEC2, c1);
        }
        #pragma unroll
        for (int i = 0; i < 16; i++) {
            float flo = __uint_as_float((unsigned)(acc[i] & 0xffffffffull));
            float fhi = __uint_as_float((unsigned)(acc[i] >> 32));
            if (flo > THRESH_F) { word |= 1u << (2 * i);     flo = 0.0f; }
            if (fhi > THRESH_F) { word |= 1u << (2 * i + 1); fhi = 0.0f; }
            acc[i] = ((unsigned long long)__float_as_uint(fhi) << 32) |
                     (unsigned long long)__float_as_uint(flo);
        }

        // ---- layer 2: masked adds over the warp's own row ----
        float dot[ODIM];
        #pragma unroll
        for (int o = 0; o < ODIM; o++) dot[o] = 0.0f;
        #pragma unroll 4
        for (int k = 0; k < 32; k++) {
            const unsigned wmask = __shfl_sync(0xffffffffu, word, k);
            if ((wmask >> lane) & 1u) {
                const int h = k * 32 + lane;
                #pragma unroll
                for (int o = 0; o < ODIM; o++) dot[o] += W2s[o * HDIM + h];
            }
        }
        #pragma unroll
        for (int o = 0; o < ODIM; o++) {
            float v = dot[o];
            v += __shfl_xor_sync(0xffffffffu, v, 16);
            v += __shfl_xor_sync(0xffffffffu, v, 8);
            v += __shfl_xor_sync(0xffffffffu, v, 4);
            v += __shfl_xor_sync(0xffffffffu, v, 2);
            v += __shfl_xor_sync(0xffffffffu, v, 1);
            float mm = 0.2f * m2r[o] + v;         // identical on all lanes
            if (mm > THRESH_F) { ssr[o] += 1.0f; mm = 0.0f; }
            m2r[o] = mm;
        }
    }

    // ---- spill state; write output on the final chunk ----
    #pragma unroll
    for (int i = 0; i < 16; i++) g_m1[mbase + i] = acc[i];
    if (lane == 0) {
        #pragma unroll
        for (int o = 0; o < ODIM; o++) {
            g_m2[(rowbase + row) * ODIM + o] = m2r[o];
            g_ss[(rowbase + row) * ODIM + o] = ssr[o];
        }
        if (t0 + TCHUNK >= TSTEPS) {
            #pragma unroll
            for (int o = 0; o < ODIM; o++)
                out[(size_t)(rowbase + row) * ODIM + o] = ssr[o] * (1.0f / TSTEPS);
        }
    }
}

// ============================================================================
extern "C" void kernel_launch(void* const* d_in, const int* in_sizes, int n_in,
                              void* d_out, int out_size) {
    const float* input  = (const float*)d_in[0];   // [8192,1,28,28] == [8192,784]
    const float* rand_u = (const float*)d_in[1];   // [50,8192,784]
    const float* W1     = (const float*)d_in[2];   // [1024,784]
    const float* W2     = (const float*)d_in[3];   // [10,1024]
    float* out = (float*)d_out;                    // [8192,10]

    static bool attr_set = false;
    if (!attr_set) {
        cudaFuncSetAttribute(gemm_kernel,
                             cudaFuncAttributeMaxDynamicSharedMemorySize, SMEM_G);
        attr_set = true;
    }

    // 1) split W1 into fp16 hi/lo (K padded to 832)
    wsplit_kernel<<<(HDIM * KPAD + 255) / 256, 256>>>(W1);

    // 2) pack all x_t into bitmasks
    xbits_kernel<<<(TSTEPS * BTOT) / 8, 256>>>(input, rand_u);

    // 3) per T-chunk: HMMA GEMM then sequential scan
    for (int c = 0; c < NCHUNKS; c++) {
        const int t0 = c * TCHUNK;
        dim3 ggrid(32 * TCHUNK, HDIM / NT);   // (800, 8)
        gemm_kernel<<<ggrid, GT, SMEM_G>>>(t0);
        scan_kernel<<<BTOT / BM2, 256>>>(W2, out, t0);
    }
}

// round 10
// speedup vs baseline: 4.7575x; 1.0445x over previous
#include <cuda_runtime.h>
#include <cuda_fp16.h>
#include <cstdint>

// ============================================================================
// Problem constants
// ============================================================================
#define TSTEPS   50
#define TCHUNK   25
#define NCHUNKS  (TSTEPS / TCHUNK)          // 2
#define BTOT     8192
#define JDIM     784
#define KPAD     832                        // 13 * 64
#define NKC      13                         // K chunks of 64
#define HDIM     1024
#define ODIM     10
#define THRESH_F 0.5f

// GEMM tiling: CTA = 256(M) x 128(N), 16 warps (8M x 2N), warp tile 32x64
#define MT 256
#define NT 128
#define GT 512                              // gemm threads

// smem layout: [xw][A0][A1][B0][B1]
#define PITCH      144                      // 64 halves (128B) padded to 144B
#define ATILE      (MT * PITCH)             // 36864
#define BTILE      (NT * PITCH)             // 18432
#define XW_BYTES   (MT * NKC * 8)           // 26624
#define OFF_A0     XW_BYTES
#define OFF_A1     (XW_BYTES + ATILE)
#define OFF_B0     (XW_BYTES + 2 * ATILE)
#define OFF_B1     (XW_BYTES + 2 * ATILE + BTILE)
#define SMEM_G     (XW_BYTES + 2 * ATILE + 2 * BTILE)   // 137216

// ============================================================================
// Static device scratch (allocation-free rule: __device__ globals)
// ============================================================================
__device__ unsigned long long g_xbits[(size_t)TSTEPS * BTOT * NKC];   // ~42.6 MB
__device__ __half g_Bhi[(size_t)HDIM * KPAD];                         // 1.7 MB
__device__ __half g_Blo[(size_t)HDIM * KPAD];                         // 1.7 MB
__device__ float  g_C[2][(size_t)TCHUNK * BTOT * HDIM];               // ~1.68 GB
__device__ unsigned long long g_m1[(size_t)BTOT * (HDIM / 2)];        // 33.5 MB
__device__ float  g_m2[BTOT * ODIM];
__device__ float  g_ss[BTOT * ODIM];

// ============================================================================
// Kernel 1: split W1 into fp16 hi + scaled fp16 lo, pad K 784->832 with zeros
// ============================================================================
__global__ void wsplit_kernel(const float* __restrict__ W1) {
    int idx = blockIdx.x * 256 + threadIdx.x;
    if (idx >= HDIM * KPAD) return;
    int n = idx / KPAD, k = idx % KPAD;
    float w = (k < JDIM) ? W1[n * JDIM + k] : 0.0f;
    __half hi = __float2half_rn(w);
    __half lo = __float2half_rn((w - __half2float(hi)) * 2048.0f);
    g_Bhi[idx] = hi;
    g_Blo[idx] = lo;
}

// ============================================================================
// Kernel 2: pack x_t = (sample > rand_t) into 64-bit masks (13 words per row)
// ============================================================================
__global__ __launch_bounds__(256)
void xbits_kernel(const float* __restrict__ sample,
                  const float* __restrict__ rand_u) {
    const int lane = threadIdx.x & 31;
    const int wid = threadIdx.x >> 5;
    const size_t row = (size_t)blockIdx.x * 8 + wid;   // 0 .. 50*8192-1
    const int t = (int)(row / BTOT);
    const int b = (int)(row % BTOT);
    const float* s = sample + (size_t)b * JDIM;
    const float* r = rand_u + ((size_t)t * BTOT + b) * JDIM;
    unsigned long long* dst = g_xbits + row * NKC;
    #pragma unroll
    for (int w = 0; w < NKC; w++) {
        int j0 = w * 64 + lane;
        int j1 = j0 + 32;
        bool b0 = (j0 < JDIM) && (s[j0] > r[j0]);
        bool b1 = (j1 < JDIM) && (s[j1] > r[j1]);
        unsigned lo = __ballot_sync(0xffffffffu, b0);
        unsigned hi = __ballot_sync(0xffffffffu, b1);
        if (lane == 0)
            dst[w] = ((unsigned long long)hi << 32) | (unsigned long long)lo;
    }
}

// ============================================================================
// MMA / ldmatrix / cp.async helpers (portable PTX)
// ============================================================================
__device__ __forceinline__ void mma16816(float* c, const uint32_t* a,
                                         uint32_t b0, uint32_t b1) {
    asm volatile(
        "mma.sync.aligned.m16n8k16.row.col.f32.f16.f16.f32 "
        "{%0,%1,%2,%3}, {%4,%5,%6,%7}, {%8,%9}, {%0,%1,%2,%3};"
        : "+f"(c[0]), "+f"(c[1]), "+f"(c[2]), "+f"(c[3])
        : "r"(a[0]), "r"(a[1]), "r"(a[2]), "r"(a[3]), "r"(b0), "r"(b1));
}

#define LDSM_X4(r0, r1, r2, r3, addr) \
    asm volatile("ldmatrix.sync.aligned.m8n8.x4.shared.b16 {%0,%1,%2,%3}, [%4];" \
                 : "=r"(r0), "=r"(r1), "=r"(r2), "=r"(r3) : "r"(addr))

#define CP_ASYNC16(saddr, gptr) \
    asm volatile("cp.async.cg.shared.global [%0], [%1], 16;" \
                 :: "r"(saddr), "l"(gptr) : "memory")
#define CP_COMMIT() asm volatile("cp.async.commit_group;" ::: "memory")
#define CP_WAIT0()  asm volatile("cp.async.wait_group 0;" ::: "memory")

__device__ __forceinline__ uint32_t smem_u32(const void* p) {
    uint32_t a;
    asm("{ .reg .u64 t; cvta.to.shared.u64 t, %1; cvt.u32.u64 %0, t; }"
        : "=r"(a) : "l"(p));
    return a;
}

// 2 x-bits at (pos, pos+1) -> packed fp16 pair {0/1, 0/1}
__device__ __forceinline__ uint32_t pair_to_h2(uint32_t s, int pos) {
    uint32_t b = s >> pos;
    return ((b & 1u) * 0x3C00u) | ((b & 2u) * 0x1E000000u);
}

// ============================================================================
// Kernel 3: HMMA GEMM over one T-chunk.
//   MMA-first loop order + cp.async B staging (no issue-side LDG stalls).
//   C[tl, b, n] = x @ Whi^T + 2^-11 * (x @ Wlo^T)
//   grid (32*TCHUNK, 8), block 512. Pass order: lo -> acc*=2^-11 -> hi.
// ============================================================================
__global__ __launch_bounds__(GT)
void gemm_kernel(int t0, int cbuf) {
    extern __shared__ char smem[];
    unsigned long long* xw = (unsigned long long*)smem;     // [256][13]
    const uint32_t sbase = smem_u32(smem);

    const int tid = threadIdx.x;
    const int lane = tid & 31;
    const int wid = tid >> 5;           // 0..15
    const int g = lane >> 2;            // 0..7
    const int t4 = lane & 3;            // 0..3
    const int tsh = t4 * 2;
    const int mwarp = wid & 7;          // 0..7 -> 32-row M group
    const int nwarp = wid >> 3;         // 0..1 -> 64-col N group

    const int tl = blockIdx.x >> 5;          // 0..TCHUNK-1
    const int btile = blockIdx.x & 31;       // 0..31
    const int nb = blockIdx.y;               // 0..7
    const int tglob = t0 + tl;

    // decode thread mapping: row = tid>>1, half-word = tid&1
    const int drow = tid >> 1;
    const int dh = tid & 1;

    // ldmatrix per-lane row/byte offsets
    const uint32_t a_off = (uint32_t)((lane & 15) * PITCH + (lane >> 4) * 16);
    const uint32_t b_off = (uint32_t)
        (((lane & 7) + ((lane >> 4) << 3)) * PITCH + (((lane >> 3) & 1) << 4));

    // B staging indices (2 x 16B lines per thread)
    const int br0 = tid >> 3, bq0 = tid & 7;
    const int br1 = (tid + GT) >> 3, bq1 = (tid + GT) & 7;

    // ---- stage all x-bit words for this 256-row m-tile ----
    {
        const unsigned long long* src =
            g_xbits + ((size_t)tglob * BTOT + (size_t)btile * MT) * NKC;
        #pragma unroll
        for (int i = 0; i < 7; i++) {
            int idx = tid + i * GT;
            if (idx < MT * NKC) xw[idx] = src[idx];
        }
    }
    __syncthreads();

    float acc[2][8][4];
    #pragma unroll
    for (int mm = 0; mm < 2; mm++)
        #pragma unroll
        for (int nn = 0; nn < 8; nn++)
            #pragma unroll
            for (int q = 0; q < 4; q++) acc[mm][nn][q] = 0.0f;

    #pragma unroll 1
    for (int pass = 0; pass < 2; pass++) {
        const char* Bg = (const char*)((pass ? g_Bhi : g_Blo) + (size_t)nb * NT * KPAD);

        // ---- prologue: stage kb=0 into buffer 0 ----
        {
            uint32_t bits = (uint32_t)(xw[drow * NKC + 0] >> (dh << 5));
            uint4* adst = (uint4*)(smem + OFF_A0 + drow * PITCH + dh * 64);
            #pragma unroll
            for (int q = 0; q < 4; q++) {
                uint4 v;
                v.x = pair_to_h2(bits, q * 8 + 0);
                v.y = pair_to_h2(bits, q * 8 + 2);
                v.z = pair_to_h2(bits, q * 8 + 4);
                v.w = pair_to_h2(bits, q * 8 + 6);
                adst[q] = v;
            }
            CP_ASYNC16(sbase + OFF_B0 + br0 * PITCH + bq0 * 16,
                       Bg + (size_t)br0 * (KPAD * 2) + bq0 * 16);
            CP_ASYNC16(sbase + OFF_B0 + br1 * PITCH + bq1 * 16,
                       Bg + (size_t)br1 * (KPAD * 2) + bq1 * 16);
            CP_COMMIT();
        }

        #pragma unroll 1
        for (int kb = 0; kb < NKC; kb++) {
            const int buf = kb & 1;
            CP_WAIT0();
            __syncthreads();

            // ---- MMAs on current buffer (issued first) ----
            const uint32_t Ab = sbase + (buf ? OFF_A1 : OFF_A0);
            const uint32_t Bb = sbase + (buf ? OFF_B1 : OFF_B0);
            const uint32_t a0_addr = Ab + (uint32_t)(mwarp * 32) * PITCH + a_off;
            const uint32_t a1_addr = a0_addr + 16 * PITCH;
            const uint32_t bb_addr = Bb + (uint32_t)(nwarp * 64) * PITCH + b_off;

            #pragma unroll
            for (int ks = 0; ks < 4; ks++) {
                uint32_t A0[4], A1[4];
                LDSM_X4(A0[0], A0[1], A0[2], A0[3], a0_addr + ks * 32);
                LDSM_X4(A1[0], A1[1], A1[2], A1[3], a1_addr + ks * 32);
                #pragma unroll
                for (int np = 0; np < 4; np++) {
                    uint32_t B0, B1, B2, B3;
                    LDSM_X4(B0, B1, B2, B3,
                            bb_addr + (uint32_t)(np * 16) * PITCH + ks * 32);
                    mma16816(acc[0][np * 2],     A0, B0, B1);
                    mma16816(acc[1][np * 2],     A1, B0, B1);
                    mma16816(acc[0][np * 2 + 1], A0, B2, B3);
                    mma16816(acc[1][np * 2 + 1], A1, B2, B3);
                }
            }

            // ---- stage kb+1 into the other buffer (async B, ALU A) ----
            if (kb + 1 < NKC) {
                const int aoff = (buf ? OFF_A0 : OFF_A1);
                const int boff = (buf ? OFF_B0 : OFF_B1);
                uint32_t bits = (uint32_t)(xw[drow * NKC + kb + 1] >> (dh << 5));
                uint4* adst = (uint4*)(smem + aoff + drow * PITCH + dh * 64);
                #pragma unroll
                for (int q = 0; q < 4; q++) {
                    uint4 v;
                    v.x = pair_to_h2(bits, q * 8 + 0);
                    v.y = pair_to_h2(bits, q * 8 + 2);
                    v.z = pair_to_h2(bits, q * 8 + 4);
                    v.w = pair_to_h2(bits, q * 8 + 6);
                    adst[q] = v;
                }
                const char* src = Bg + (kb + 1) * 128;
                CP_ASYNC16(sbase + boff + br0 * PITCH + bq0 * 16,
                           src + (size_t)br0 * (KPAD * 2) + bq0 * 16);
                CP_ASYNC16(sbase + boff + br1 * PITCH + bq1 * 16,
                           src + (size_t)br1 * (KPAD * 2) + bq1 * 16);
                CP_COMMIT();
            }
        }
        __syncthreads();   // protect buffers before next pass's prologue

        if (pass == 0) {
            #pragma unroll
            for (int mm = 0; mm < 2; mm++)
                #pragma unroll
                for (int nn = 0; nn < 8; nn++)
                    #pragma unroll
                    for (int q = 0; q < 4; q++)
                        acc[mm][nn][q] *= (1.0f / 2048.0f);
        }
    }

    // ---- epilogue: write fp32 C ----
    float* Cg = g_C[cbuf];
    const size_t rowbase = (size_t)tl * BTOT + (size_t)btile * MT + mwarp * 32;
    const int colbase = nb * NT + nwarp * 64 + tsh;
    #pragma unroll
    for (int mm = 0; mm < 2; mm++) {
        float* r0 = Cg + (rowbase + mm * 16 + g) * HDIM + colbase;
        float* r1 = r0 + 8 * HDIM;
        #pragma unroll
        for (int nn = 0; nn < 8; nn++) {
            *(float2*)(r0 + nn * 8) = make_float2(acc[mm][nn][0], acc[mm][nn][1]);
            *(float2*)(r1 + nn * 8) = make_float2(acc[mm][nn][2], acc[mm][nn][3]);
        }
    }
}

// Packed fp32x2 helpers (scan kernel)
#define FMA_DECAY_F32X2(acc, dec2, c2) \
    asm("fma.rn.f32x2 %0, %0, %1, %2;" : "+l"(acc) : "l"(dec2), "l"(c2))
#define PACK64(lo32, hi32, dst) \
    asm("mov.b64 %0, {%1, %2};" : "=l"(dst) : "r"(lo32), "r"(hi32))

// ============================================================================
// Kernel 4: sequential membrane scan over one T-chunk.
//   Warp owns its batch row; no __syncthreads in the time loop.
//   W2 transposed in smem with pitch 12 floats: per active h, 3x LDS.128
//   (conflict-free within each 8-lane phase) instead of 10 scalar LDS.
// ============================================================================
#define BM2 8
#define W2P 12
__global__ __launch_bounds__(256, 2)
void scan_kernel(const float* __restrict__ W2, float* __restrict__ out,
                 int t0, int cbuf) {
    __shared__ float W2t[HDIM * W2P];         // 48 KB: [h][o(0..9), pad, pad]

    const int tid = threadIdx.x;
    const int lane = tid & 31;
    const int row = tid >> 5;                 // warp id == batch row in tile
    const int rowbase = blockIdx.x * BM2;
    const float* Cg = g_C[cbuf];

    for (int i = tid; i < HDIM * W2P; i += 256) {
        int h = i / W2P, o = i % W2P;
        W2t[i] = (o < ODIM) ? W2[o * HDIM + h] : 0.0f;
    }

    // ---- state ----
    unsigned long long acc[16];
    float m2r[ODIM], ssr[ODIM];
    const size_t mbase = (size_t)(rowbase + row) * (HDIM / 2) + lane * 16;
    if (t0 == 0) {
        #pragma unroll
        for (int i = 0; i < 16; i++) acc[i] = 0ull;
        #pragma unroll
        for (int o = 0; o < ODIM; o++) { m2r[o] = 0.0f; ssr[o] = 0.0f; }
    } else {
        #pragma unroll
        for (int i = 0; i < 16; i++) acc[i] = g_m1[mbase + i];
        #pragma unroll
        for (int o = 0; o < ODIM; o++) {
            m2r[o] = g_m2[(rowbase + row) * ODIM + o];
            ssr[o] = g_ss[(rowbase + row) * ODIM + o];
        }
    }
    const unsigned long long DEC2 = 0x3E4CCCCD3E4CCCCDull;   // (0.2f, 0.2f)
    __syncthreads();   // W2t ready

    const size_t rowoff = (size_t)(rowbase + row) * HDIM + lane * 32;

    uint4 bufA[8], bufB[8];
    {   // prime: load C_{t0}
        const uint4* p = (const uint4*)(Cg + rowoff);
        #pragma unroll
        for (int q = 0; q < 8; q++) bufA[q] = __ldcs(p + q);
    }

    #pragma unroll 1
    for (int tt = 0; tt < TCHUNK; tt++) {
        // prefetch next step's C row into the idle buffer
        uint4* cur = (tt & 1) ? bufB : bufA;
        uint4* nxt = (tt & 1) ? bufA : bufB;
        if (tt + 1 < TCHUNK) {
            const uint4* p = (const uint4*)
                (Cg + (size_t)(tt + 1) * BTOT * HDIM + rowoff);
            #pragma unroll
            for (int q = 0; q < 8; q++) nxt[q] = __ldcs(p + q);
        }

        // ---- m1 = decay*m1 + C_t; spike; reset; pack 32 bits ----
        unsigned word = 0;
        #pragma unroll
        for (int q = 0; q < 8; q++) {
            unsigned long long c0, c1;
            PACK64(cur[q].x, cur[q].y, c0);
            PACK64(cur[q].z, cur[q].w, c1);
            FMA_DECAY_F32X2(acc[2 * q],     DEC2, c0);
            FMA_DECAY_F32X2(acc[2 * q + 1], DEC2, c1);
        }
        #pragma unroll
        for (int i = 0; i < 16; i++) {
            float flo = __uint_as_float((unsigned)(acc[i] & 0xffffffffull));
            float fhi = __uint_as_float((unsigned)(acc[i] >> 32));
            if (flo > THRESH_F) { word |= 1u << (2 * i);     flo = 0.0f; }
            if (fhi > THRESH_F) { word |= 1u << (2 * i + 1); fhi = 0.0f; }
            acc[i] = ((unsigned long long)__float_as_uint(fhi) << 32) |
                     (unsigned long long)__float_as_uint(flo);
        }

        // ---- layer 2: vectorized masked adds over the warp's own row ----
        float4 d0 = make_float4(0.f, 0.f, 0.f, 0.f);
        float4 d1 = make_float4(0.f, 0.f, 0.f, 0.f);
        float4 d2 = make_float4(0.f, 0.f, 0.f, 0.f);
        #pragma unroll 4
        for (int k = 0; k < 32; k++) {
            const unsigned wmask = __shfl_sync(0xffffffffu, word, k);
            if ((wmask >> lane) & 1u) {
                const float4* p = (const float4*)(W2t + (k * 32 + lane) * W2P);
                float4 x0 = p[0], x1 = p[1], x2 = p[2];
                d0.x += x0.x; d0.y += x0.y; d0.z += x0.z; d0.w += x0.w;
                d1.x += x1.x; d1.y += x1.y; d1.z += x1.z; d1.w += x1.w;
                d2.x += x2.x; d2.y += x2.y;               // o8, o9
            }
        }
        float dot[ODIM] = { d0.x, d0.y, d0.z, d0.w,
                            d1.x, d1.y, d1.z, d1.w, d2.x, d2.y };
        #pragma unroll
        for (int o = 0; o < ODIM; o++) {
            float v = dot[o];
            v += __shfl_xor_sync(0xffffffffu, v, 16);
            v += __shfl_xor_sync(0xffffffffu, v, 8);
            v += __shfl_xor_sync(0xffffffffu, v, 4);
            v += __shfl_xor_sync(0xffffffffu, v, 2);
            v += __shfl_xor_sync(0xffffffffu, v, 1);
            float mm = 0.2f * m2r[o] + v;         // identical on all lanes
            if (mm > THRESH_F) { ssr[o] += 1.0f; mm = 0.0f; }
            m2r[o] = mm;
        }
    }

    // ---- spill state; write output on the final chunk ----
    #pragma unroll
    for (int i = 0; i < 16; i++) g_m1[mbase + i] = acc[i];
    if (lane == 0) {
        #pragma unroll
        for (int o = 0; o < ODIM; o++) {
            g_m2[(rowbase + row) * ODIM + o] = m2r[o];
            g_ss[(rowbase + row) * ODIM + o] = ssr[o];
        }
        if (t0 + TCHUNK >= TSTEPS) {
            #pragma unroll
            for (int o = 0; o < ODIM; o++)
                out[(size_t)(rowbase + row) * ODIM + o] = ssr[o] * (1.0f / TSTEPS);
        }
    }
}

// ============================================================================
extern "C" void kernel_launch(void* const* d_in, const int* in_sizes, int n_in,
                              void* d_out, int out_size) {
    const float* input  = (const float*)d_in[0];   // [8192,1,28,28] == [8192,784]
    const float* rand_u = (const float*)d_in[1];   // [50,8192,784]
    const float* W1     = (const float*)d_in[2];   // [1024,784]
    const float* W2     = (const float*)d_in[3];   // [10,1024]
    float* out = (float*)d_out;                    // [8192,10]

    // one-time setup (first call is the uncaptured correctness run)
    static bool init_done = false;
    static cudaStream_t s2 = nullptr;
    static cudaEvent_t ev0 = nullptr, ev1 = nullptr;
    if (!init_done) {
        cudaFuncSetAttribute(gemm_kernel,
                             cudaFuncAttributeMaxDynamicSharedMemorySize, SMEM_G);
        cudaStreamCreateWithFlags(&s2, cudaStreamNonBlocking);
        cudaEventCreateWithFlags(&ev0, cudaEventDisableTiming);
        cudaEventCreateWithFlags(&ev1, cudaEventDisableTiming);
        init_done = true;
    }

    dim3 ggrid(32 * TCHUNK, HDIM / NT);   // (800, 8)

    // 1) weight split + x bit-packing (stream 0)
    wsplit_kernel<<<(HDIM * KPAD + 255) / 256, 256>>>(W1);
    xbits_kernel<<<(TSTEPS * BTOT) / 8, 256>>>(input, rand_u);

    // 2) chunk 0 GEMM (stream 0)
    gemm_kernel<<<ggrid, GT, SMEM_G>>>(0, 0);
    cudaEventRecord(ev0, 0);

    // 3) chunk 1 GEMM on side stream, overlapping chunk 0 scan
    cudaStreamWaitEvent(s2, ev0, 0);
    gemm_kernel<<<ggrid, GT, SMEM_G, s2>>>(TCHUNK, 1);
    cudaEventRecord(ev1, s2);

    // 4) chunk 0 scan (stream 0) — concurrent with chunk 1 GEMM
    scan_kernel<<<BTOT / BM2, 256>>>(W2, out, 0, 0);

    // 5) join, then chunk 1 scan
    cudaStreamWaitEvent(0, ev1, 0);
    scan_kernel<<<BTOT / BM2, 256>>>(W2, out, TCHUNK, 1);
}

// round 11
// speedup vs baseline: 5.5837x; 1.1736x over previous
#include <cuda_runtime.h>
#include <cuda_fp16.h>
#include <cstdint>

// ============================================================================
// Problem constants
// ============================================================================
#define TSTEPS   50
#define TCHUNK   25
#define NCHUNKS  (TSTEPS / TCHUNK)          // 2
#define BTOT     8192
#define JDIM     784
#define KPAD     832                        // 13 * 64
#define NKC      13                         // K chunks of 64
#define HDIM     1024
#define ODIM     10
#define THRESH_F 0.5f

// GEMM tiling: CTA = 256(M) x 128(N), 16 warps (8M x 2N), warp tile 32x64
#define MT 256
#define NT 128
#define GT 512                              // gemm threads

// smem layout: [xw][A0][A1][BH0][BL0][BH1][BL1]
#define PITCH      144                      // 64 halves (128B) padded to 144B
#define ATILE      (MT * PITCH)             // 36864
#define BTILE      (NT * PITCH)             // 18432
#define XW_BYTES   (MT * NKC * 8)           // 26624
#define OFF_A0     XW_BYTES
#define OFF_A1     (OFF_A0 + ATILE)
#define OFF_BH0    (OFF_A1 + ATILE)
#define OFF_BL0    (OFF_BH0 + BTILE)
#define OFF_BH1    (OFF_BL0 + BTILE)
#define OFF_BL1    (OFF_BH1 + BTILE)
#define SMEM_G     (OFF_BL1 + BTILE)        // 174080

// ============================================================================
// Static device scratch (allocation-free rule: __device__ globals)
// ============================================================================
__device__ unsigned long long g_xbits[(size_t)TSTEPS * BTOT * NKC];   // ~42.6 MB
__device__ __half g_Bhi[(size_t)HDIM * KPAD];                         // fp16(w)*2048
__device__ __half g_Blo[(size_t)HDIM * KPAD];                         // (w-hi)*2048
__device__ float  g_C[2][(size_t)TCHUNK * BTOT * HDIM];               // ~1.68 GB
__device__ unsigned long long g_m1[(size_t)BTOT * (HDIM / 2)];        // 33.5 MB
__device__ float  g_m2[BTOT * ODIM];
__device__ float  g_ss[BTOT * ODIM];

// ============================================================================
// Kernel 1: split W1. Bhi = fp16(w)*2^11 (exact scale), Blo = (w-fp16(w))*2^11.
// Final C = (x@Bhi^T + x@Blo^T) * 2^-11  ==  x@fp16(w)^T + x@residual^T.
// ============================================================================
__global__ void wsplit_kernel(const float* __restrict__ W1) {
    int idx = blockIdx.x * 256 + threadIdx.x;
    if (idx >= HDIM * KPAD) return;
    int n = idx / KPAD, k = idx % KPAD;
    float w = (k < JDIM) ? W1[n * JDIM + k] : 0.0f;
    __half hi = __float2half_rn(w);
    float hif = __half2float(hi);
    g_Bhi[idx] = __float2half_rn(hif * 2048.0f);          // exact (pow2 scale)
    g_Blo[idx] = __float2half_rn((w - hif) * 2048.0f);
}

// ============================================================================
// Kernel 2: pack x_t = (sample > rand_t) into 64-bit masks (13 words per row)
// ============================================================================
__global__ __launch_bounds__(256)
void xbits_kernel(const float* __restrict__ sample,
                  const float* __restrict__ rand_u) {
    const int lane = threadIdx.x & 31;
    const int wid = threadIdx.x >> 5;
    const size_t row = (size_t)blockIdx.x * 8 + wid;   // 0 .. 50*8192-1
    const int t = (int)(row / BTOT);
    const int b = (int)(row % BTOT);
    const float* s = sample + (size_t)b * JDIM;
    const float* r = rand_u + ((size_t)t * BTOT + b) * JDIM;
    unsigned long long* dst = g_xbits + row * NKC;
    #pragma unroll
    for (int w = 0; w < NKC; w++) {
        int j0 = w * 64 + lane;
        int j1 = j0 + 32;
        bool b0 = (j0 < JDIM) && (s[j0] > r[j0]);
        bool b1 = (j1 < JDIM) && (s[j1] > r[j1]);
        unsigned lo = __ballot_sync(0xffffffffu, b0);
        unsigned hi = __ballot_sync(0xffffffffu, b1);
        if (lane == 0)
            dst[w] = ((unsigned long long)hi << 32) | (unsigned long long)lo;
    }
}

// ============================================================================
// MMA / ldmatrix / cp.async helpers (portable PTX)
// ============================================================================
__device__ __forceinline__ void mma16816(float* c, const uint32_t* a,
                                         uint32_t b0, uint32_t b1) {
    asm volatile(
        "mma.sync.aligned.m16n8k16.row.col.f32.f16.f16.f32 "
        "{%0,%1,%2,%3}, {%4,%5,%6,%7}, {%8,%9}, {%0,%1,%2,%3};"
        : "+f"(c[0]), "+f"(c[1]), "+f"(c[2]), "+f"(c[3])
        : "r"(a[0]), "r"(a[1]), "r"(a[2]), "r"(a[3]), "r"(b0), "r"(b1));
}

#define LDSM_X4(r0, r1, r2, r3, addr) \
    asm volatile("ldmatrix.sync.aligned.m8n8.x4.shared.b16 {%0,%1,%2,%3}, [%4];" \
                 : "=r"(r0), "=r"(r1), "=r"(r2), "=r"(r3) : "r"(addr))

#define CP_ASYNC16(saddr, gptr) \
    asm volatile("cp.async.cg.shared.global [%0], [%1], 16;" \
                 :: "r"(saddr), "l"(gptr) : "memory")
#define CP_COMMIT() asm volatile("cp.async.commit_group;" ::: "memory")
#define CP_WAIT0()  asm volatile("cp.async.wait_group 0;" ::: "memory")

__device__ __forceinline__ uint32_t smem_u32(const void* p) {
    uint32_t a;
    asm("{ .reg .u64 t; cvta.to.shared.u64 t, %1; cvt.u32.u64 %0, t; }"
        : "=r"(a) : "l"(p));
    return a;
}

// 2 x-bits at (pos, pos+1) -> packed fp16 pair {0/1, 0/1}
__device__ __forceinline__ uint32_t pair_to_h2(uint32_t s, int pos) {
    uint32_t b = s >> pos;
    return ((b & 1u) * 0x3C00u) | ((b & 2u) * 0x1E000000u);
}

// ============================================================================
// Kernel 3: fused single-pass HMMA GEMM over one T-chunk.
//   acc = x@Bhi'^T + x@Blo^T  (Bhi' pre-scaled 2^11);  C = acc * 2^-11.
//   A tile decoded once per kb; A fragments reused for hi AND lo MMAs.
//   grid (32*TCHUNK, 8), block 512.
// ============================================================================
__global__ __launch_bounds__(GT)
void gemm_kernel(int t0, int cbuf) {
    extern __shared__ char smem[];
    unsigned long long* xw = (unsigned long long*)smem;     // [256][13]
    const uint32_t sbase = smem_u32(smem);

    const int tid = threadIdx.x;
    const int lane = tid & 31;
    const int wid = tid >> 5;           // 0..15
    const int g = lane >> 2;            // 0..7
    const int t4 = lane & 3;            // 0..3
    const int tsh = t4 * 2;
    const int mwarp = wid & 7;          // 0..7 -> 32-row M group
    const int nwarp = wid >> 3;         // 0..1 -> 64-col N group

    const int tl = blockIdx.x >> 5;          // 0..TCHUNK-1
    const int btile = blockIdx.x & 31;       // 0..31
    const int nb = blockIdx.y;               // 0..7
    const int tglob = t0 + tl;

    // decode thread mapping: row = tid>>1, half-word = tid&1
    const int drow = tid >> 1;
    const int dh = tid & 1;

    // ldmatrix per-lane row/byte offsets
    const uint32_t a_off = (uint32_t)((lane & 15) * PITCH + (lane >> 4) * 16);
    const uint32_t b_off = (uint32_t)
        (((lane & 7) + ((lane >> 4) << 3)) * PITCH + (((lane >> 3) & 1) << 4));

    // B staging indices (2 x 16B lines per tile per thread)
    const int br0 = tid >> 3, bq0 = tid & 7;
    const int br1 = (tid + GT) >> 3, bq1 = (tid + GT) & 7;

    const char* BgH = (const char*)(g_Bhi + (size_t)nb * NT * KPAD);
    const char* BgL = (const char*)(g_Blo + (size_t)nb * NT * KPAD);

    // ---- stage all x-bit words for this 256-row m-tile ----
    {
        const unsigned long long* src =
            g_xbits + ((size_t)tglob * BTOT + (size_t)btile * MT) * NKC;
        #pragma unroll
        for (int i = 0; i < 7; i++) {
            int idx = tid + i * GT;
            if (idx < MT * NKC) xw[idx] = src[idx];
        }
    }
    __syncthreads();

    float acc[2][8][4];
    #pragma unroll
    for (int mm = 0; mm < 2; mm++)
        #pragma unroll
        for (int nn = 0; nn < 8; nn++)
            #pragma unroll
            for (int q = 0; q < 4; q++) acc[mm][nn][q] = 0.0f;

    // ---- prologue: stage kb=0 into buffer 0 ----
    {
        uint32_t bits = (uint32_t)(xw[drow * NKC + 0] >> (dh << 5));
        uint4* adst = (uint4*)(smem + OFF_A0 + drow * PITCH + dh * 64);
        #pragma unroll
        for (int q = 0; q < 4; q++) {
            uint4 v;
            v.x = pair_to_h2(bits, q * 8 + 0);
            v.y = pair_to_h2(bits, q * 8 + 2);
            v.z = pair_to_h2(bits, q * 8 + 4);
            v.w = pair_to_h2(bits, q * 8 + 6);
            adst[q] = v;
        }
        CP_ASYNC16(sbase + OFF_BH0 + br0 * PITCH + bq0 * 16,
                   BgH + (size_t)br0 * (KPAD * 2) + bq0 * 16);
        CP_ASYNC16(sbase + OFF_BH0 + br1 * PITCH + bq1 * 16,
                   BgH + (size_t)br1 * (KPAD * 2) + bq1 * 16);
        CP_ASYNC16(sbase + OFF_BL0 + br0 * PITCH + bq0 * 16,
                   BgL + (size_t)br0 * (KPAD * 2) + bq0 * 16);
        CP_ASYNC16(sbase + OFF_BL0 + br1 * PITCH + bq1 * 16,
                   BgL + (size_t)br1 * (KPAD * 2) + bq1 * 16);
        CP_COMMIT();
    }

    #pragma unroll 1
    for (int kb = 0; kb < NKC; kb++) {
        const int buf = kb & 1;
        CP_WAIT0();
        __syncthreads();

        // ---- MMAs on current buffer: A fragments shared by hi & lo ----
        const uint32_t Ab  = sbase + (buf ? OFF_A1  : OFF_A0);
        const uint32_t BbH = sbase + (buf ? OFF_BH1 : OFF_BH0);
        const uint32_t BbL = sbase + (buf ? OFF_BL1 : OFF_BL0);
        const uint32_t a0_addr = Ab + (uint32_t)(mwarp * 32) * PITCH + a_off;
        const uint32_t a1_addr = a0_addr + 16 * PITCH;
        const uint32_t bh_addr = BbH + (uint32_t)(nwarp * 64) * PITCH + b_off;
        const uint32_t bl_addr = BbL + (uint32_t)(nwarp * 64) * PITCH + b_off;

        #pragma unroll
        for (int ks = 0; ks < 4; ks++) {
            uint32_t A0[4], A1[4];
            LDSM_X4(A0[0], A0[1], A0[2], A0[3], a0_addr + ks * 32);
            LDSM_X4(A1[0], A1[1], A1[2], A1[3], a1_addr + ks * 32);
            #pragma unroll
            for (int np = 0; np < 4; np++) {
                uint32_t B0, B1, B2, B3;
                LDSM_X4(B0, B1, B2, B3,
                        bh_addr + (uint32_t)(np * 16) * PITCH + ks * 32);
                mma16816(acc[0][np * 2],     A0, B0, B1);
                mma16816(acc[1][np * 2],     A1, B0, B1);
                mma16816(acc[0][np * 2 + 1], A0, B2, B3);
                mma16816(acc[1][np * 2 + 1], A1, B2, B3);
            }
            #pragma unroll
            for (int np = 0; np < 4; np++) {
                uint32_t B0, B1, B2, B3;
                LDSM_X4(B0, B1, B2, B3,
                        bl_addr + (uint32_t)(np * 16) * PITCH + ks * 32);
                mma16816(acc[0][np * 2],     A0, B0, B1);
                mma16816(acc[1][np * 2],     A1, B0, B1);
                mma16816(acc[0][np * 2 + 1], A0, B2, B3);
                mma16816(acc[1][np * 2 + 1], A1, B2, B3);
            }
        }

        // ---- stage kb+1 into the other buffer (async B, ALU A) ----
        if (kb + 1 < NKC) {
            const int aoff = (buf ? OFF_A0 : OFF_A1);
            const int bhoff = (buf ? OFF_BH0 : OFF_BH1);
            const int bloff = (buf ? OFF_BL0 : OFF_BL1);
            uint32_t bits = (uint32_t)(xw[drow * NKC + kb + 1] >> (dh << 5));
            uint4* adst = (uint4*)(smem + aoff + drow * PITCH + dh * 64);
            #pragma unroll
            for (int q = 0; q < 4; q++) {
                uint4 v;
                v.x = pair_to_h2(bits, q * 8 + 0);
                v.y = pair_to_h2(bits, q * 8 + 2);
                v.z = pair_to_h2(bits, q * 8 + 4);
                v.w = pair_to_h2(bits, q * 8 + 6);
                adst[q] = v;
            }
            const char* srcH = BgH + (kb + 1) * 128;
            const char* srcL = BgL + (kb + 1) * 128;
            CP_ASYNC16(sbase + bhoff + br0 * PITCH + bq0 * 16,
                       srcH + (size_t)br0 * (KPAD * 2) + bq0 * 16);
            CP_ASYNC16(sbase + bhoff + br1 * PITCH + bq1 * 16,
                       srcH + (size_t)br1 * (KPAD * 2) + bq1 * 16);
            CP_ASYNC16(sbase + bloff + br0 * PITCH + bq0 * 16,
                       srcL + (size_t)br0 * (KPAD * 2) + bq0 * 16);
            CP_ASYNC16(sbase + bloff + br1 * PITCH + bq1 * 16,
                       srcL + (size_t)br1 * (KPAD * 2) + bq1 * 16);
            CP_COMMIT();
        }
    }

    // ---- epilogue: C = acc * 2^-11 ----
    float* Cg = g_C[cbuf];
    const size_t rowbase = (size_t)tl * BTOT + (size_t)btile * MT + mwarp * 32;
    const int colbase = nb * NT + nwarp * 64 + tsh;
    #pragma unroll
    for (int mm = 0; mm < 2; mm++) {
        float* r0 = Cg + (rowbase + mm * 16 + g) * HDIM + colbase;
        float* r1 = r0 + 8 * HDIM;
        #pragma unroll
        for (int nn = 0; nn < 8; nn++) {
            *(float2*)(r0 + nn * 8) =
                make_float2(acc[mm][nn][0] * (1.0f / 2048.0f),
                            acc[mm][nn][1] * (1.0f / 2048.0f));
            *(float2*)(r1 + nn * 8) =
                make_float2(acc[mm][nn][2] * (1.0f / 2048.0f),
                            acc[mm][nn][3] * (1.0f / 2048.0f));
        }
    }
}

// Packed fp32x2 helpers (scan kernel)
#define FMA_DECAY_F32X2(acc, dec2, c2) \
    asm("fma.rn.f32x2 %0, %0, %1, %2;" : "+l"(acc) : "l"(dec2), "l"(c2))
#define PACK64(lo32, hi32, dst) \
    asm("mov.b64 %0, {%1, %2};" : "=l"(dst) : "r"(lo32), "r"(hi32))

// ============================================================================
// Kernel 4: sequential membrane scan over one T-chunk.
//   Warp owns its batch row. COALESCED lane-interleaved h-ownership:
//     lane l owns h = 128q + 4l + j   (q=0..7, j=0..3)
//   so each C load instruction covers 512 contiguous bytes.
//   word bit (4q+j) <-> h = 128q + 4l + j. acc[2q]=(j0,j1), acc[2q+1]=(j2,j3).
// ============================================================================
#define BM2 8
#define W2P 12
__global__ __launch_bounds__(256, 2)
void scan_kernel(const float* __restrict__ W2, float* __restrict__ out,
                 int t0, int cbuf) {
    __shared__ float W2t[HDIM * W2P];         // 48 KB: [h][o(0..9), pad, pad]

    const int tid = threadIdx.x;
    const int lane = tid & 31;
    const int row = tid >> 5;                 // warp id == batch row in tile
    const int rowbase = blockIdx.x * BM2;
    const float* Cg = g_C[cbuf];

    for (int i = tid; i < HDIM * W2P; i += 256) {
        int h = i / W2P, o = i % W2P;
        W2t[i] = (o < ODIM) ? W2[o * HDIM + h] : 0.0f;
    }

    // ---- state ----
    unsigned long long acc[16];
    float m2r[ODIM], ssr[ODIM];
    const size_t mbase = ((size_t)(rowbase + row) * 32 + lane) * 16;
    if (t0 == 0) {
        #pragma unroll
        for (int i = 0; i < 16; i++) acc[i] = 0ull;
        #pragma unroll
        for (int o = 0; o < ODIM; o++) { m2r[o] = 0.0f; ssr[o] = 0.0f; }
    } else {
        #pragma unroll
        for (int i = 0; i < 16; i++) acc[i] = g_m1[mbase + i];
        #pragma unroll
        for (int o = 0; o < ODIM; o++) {
            m2r[o] = g_m2[(rowbase + row) * ODIM + o];
            ssr[o] = g_ss[(rowbase + row) * ODIM + o];
        }
    }
    const unsigned long long DEC2 = 0x3E4CCCCD3E4CCCCDull;   // (0.2f, 0.2f)
    __syncthreads();   // W2t ready

    // coalesced base: lane*4 floats; q-th load at +q*128 floats
    const size_t rowoff = (size_t)(rowbase + row) * HDIM + lane * 4;
    const int hb = ((lane >> 2) << 7) + (lane & 3);   // layer-2 lane h-base

    uint4 bufA[8], bufB[8];
    {   // prime: load C_{t0}
        const float* p = Cg + rowoff;
        #pragma unroll
        for (int q = 0; q < 8; q++) bufA[q] = __ldcs((const uint4*)(p + q * 128));
    }

    #pragma unroll 1
    for (int tt = 0; tt < TCHUNK; tt++) {
        uint4* cur = (tt & 1) ? bufB : bufA;
        uint4* nxt = (tt & 1) ? bufA : bufB;
        if (tt + 1 < TCHUNK) {
            const float* p = Cg + (size_t)(tt + 1) * BTOT * HDIM + rowoff;
            #pragma unroll
            for (int q = 0; q < 8; q++) nxt[q] = __ldcs((const uint4*)(p + q * 128));
        }

        // ---- m1 = decay*m1 + C_t; spike; reset; pack 32 bits ----
        unsigned word = 0;
        #pragma unroll
        for (int q = 0; q < 8; q++) {
            unsigned long long c0, c1;
            PACK64(cur[q].x, cur[q].y, c0);
            PACK64(cur[q].z, cur[q].w, c1);
            FMA_DECAY_F32X2(acc[2 * q],     DEC2, c0);
            FMA_DECAY_F32X2(acc[2 * q + 1], DEC2, c1);
        }
        #pragma unroll
        for (int i = 0; i < 16; i++) {
            float flo = __uint_as_float((unsigned)(acc[i] & 0xffffffffull));
            float fhi = __uint_as_float((unsigned)(acc[i] >> 32));
            if (flo > THRESH_F) { word |= 1u << (2 * i);     flo = 0.0f; }
            if (fhi > THRESH_F) { word |= 1u << (2 * i + 1); fhi = 0.0f; }
            acc[i] = ((unsigned long long)__float_as_uint(fhi) << 32) |
                     (unsigned long long)__float_as_uint(flo);
        }

        // ---- layer 2: lane i consumes bit i of lane-k's word ----
        float4 d0 = make_float4(0.f, 0.f, 0.f, 0.f);
        float4 d1 = make_float4(0.f, 0.f, 0.f, 0.f);
        float4 d2 = make_float4(0.f, 0.f, 0.f, 0.f);
        #pragma unroll 4
        for (int k = 0; k < 32; k++) {
            const unsigned wmask = __shfl_sync(0xffffffffu, word, k);
            if ((wmask >> lane) & 1u) {
                const int h = hb + 4 * k;     // 128*(lane>>2) + 4k + (lane&3)
                const float4* p = (const float4*)(W2t + h * W2P);
                float4 x0 = p[0], x1 = p[1], x2 = p[2];
                d0.x += x0.x; d0.y += x0.y; d0.z += x0.z; d0.w += x0.w;
                d1.x += x1.x; d1.y += x1.y; d1.z += x1.z; d1.w += x1.w;
                d2.x += x2.x; d2.y += x2.y;               // o8, o9
            }
        }
        float dot[ODIM] = { d0.x, d0.y, d0.z, d0.w,
                            d1.x, d1.y, d1.z, d1.w, d2.x, d2.y };
        #pragma unroll
        for (int o = 0; o < ODIM; o++) {
            float v = dot[o];
            v += __shfl_xor_sync(0xffffffffu, v, 16);
            v += __shfl_xor_sync(0xffffffffu, v, 8);
            v += __shfl_xor_sync(0xffffffffu, v, 4);
            v += __shfl_xor_sync(0xffffffffu, v, 2);
            v += __shfl_xor_sync(0xffffffffu, v, 1);
            float mm = 0.2f * m2r[o] + v;         // identical on all lanes
            if (mm > THRESH_F) { ssr[o] += 1.0f; mm = 0.0f; }
            m2r[o] = mm;
        }
    }

    // ---- spill state; write output on the final chunk ----
    #pragma unroll
    for (int i = 0; i < 16; i++) g_m1[mbase + i] = acc[i];
    if (lane == 0) {
        #pragma unroll
        for (int o = 0; o < ODIM; o++) {
            g_m2[(rowbase + row) * ODIM + o] = m2r[o];
            g_ss[(rowbase + row) * ODIM + o] = ssr[o];
        }
        if (t0 + TCHUNK >= TSTEPS) {
            #pragma unroll
            for (int o = 0; o < ODIM; o++)
                out[(size_t)(rowbase + row) * ODIM + o] = ssr[o] * (1.0f / TSTEPS);
        }
    }
}

// ============================================================================
extern "C" void kernel_launch(void* const* d_in, const int* in_sizes, int n_in,
                              void* d_out, int out_size) {
    const float* input  = (const float*)d_in[0];   // [8192,1,28,28] == [8192,784]
    const float* rand_u = (const float*)d_in[1];   // [50,8192,784]
    const float* W1     = (const float*)d_in[2];   // [1024,784]
    const float* W2     = (const float*)d_in[3];   // [10,1024]
    float* out = (float*)d_out;                    // [8192,10]

    // one-time setup (first call is the uncaptured correctness run)
    static bool init_done = false;
    static cudaStream_t s2 = nullptr;
    static cudaEvent_t ev0 = nullptr, ev1 = nullptr;
    if (!init_done) {
        cudaFuncSetAttribute(gemm_kernel,
                             cudaFuncAttributeMaxDynamicSharedMemorySize, SMEM_G);
        cudaStreamCreateWithFlags(&s2, cudaStreamNonBlocking);
        cudaEventCreateWithFlags(&ev0, cudaEventDisableTiming);
        cudaEventCreateWithFlags(&ev1, cudaEventDisableTiming);
        init_done = true;
    }

    dim3 ggrid(32 * TCHUNK, HDIM / NT);   // (800, 8)

    // 1) weight split + x bit-packing (stream 0)
    wsplit_kernel<<<(HDIM * KPAD + 255) / 256, 256>>>(W1);
    xbits_kernel<<<(TSTEPS * BTOT) / 8, 256>>>(input, rand_u);

    // 2) chunk 0 GEMM (stream 0)
    gemm_kernel<<<ggrid, GT, SMEM_G>>>(0, 0);
    cudaEventRecord(ev0, 0);

    // 3) chunk 1 GEMM on side stream, overlapping chunk 0 scan
    cudaStreamWaitEvent(s2, ev0, 0);
    gemm_kernel<<<ggrid, GT, SMEM_G, s2>>>(TCHUNK, 1);
    cudaEventRecord(ev1, s2);

    // 4) chunk 0 scan (stream 0) — concurrent with chunk 1 GEMM
    scan_kernel<<<BTOT / BM2, 256>>>(W2, out, 0, 0);

    // 5) join, then chunk 1 scan
    cudaStreamWaitEvent(0, ev1, 0);
    scan_kernel<<<BTOT / BM2, 256>>>(W2, out, TCHUNK, 1);
}

// round 15
// speedup vs baseline: 5.8611x; 1.0497x over previous
#include <cuda_runtime.h>
#include <cuda_fp16.h>
#include <cstdint>

// ============================================================================
// Problem constants
// ============================================================================
#define TSTEPS   50
#define BTOT     8192
#define JDIM     784
#define KPAD     832                        // 13 * 64
#define NKC      13                         // K chunks of 64
#define HDIM     1024
#define ODIM     10
#define THRESH_F 0.5f

// Chunk schedule (pure scheduling — C is indexed by absolute t)
#define C0 20
#define C1 20
#define C2 10

// GEMM tiling: CTA = 256(M) x 128(N), 16 warps (8M x 2N), warp tile 32x64
#define MT 256
#define NT 128
#define GT 512                              // gemm threads

// smem layout: [xw][A0][A1][B stages x3 (BH,BL)]
#define PITCH      144                      // 64 halves (128B) padded to 144B
#define ATILE      (MT * PITCH)             // 36864
#define BTILE      (NT * PITCH)             // 18432
#define XW_BYTES   (MT * NKC * 8)           // 26624
#define OFF_A0     XW_BYTES
#define OFF_A1     (OFF_A0 + ATILE)
#define BBASE      (OFF_A1 + ATILE)         // 100352
#define BSTAGE     (2 * BTILE)              // 36864 per stage (BH + BL)
#define SMEM_G     (BBASE + 3 * BSTAGE)     // 210944

// ============================================================================
// Static device scratch (allocation-free rule: __device__ globals)
// ============================================================================
__device__ unsigned long long g_xbits[(size_t)TSTEPS * BTOT * NKC];   // ~42.6 MB
__device__ __half g_Bhi[(size_t)HDIM * KPAD];                         // fp16(w)*2048
__device__ __half g_Blo[(size_t)HDIM * KPAD];                         // (w-hi)*2048
__device__ float  g_C[(size_t)TSTEPS * BTOT * HDIM];                  // ~1.68 GB
__device__ unsigned long long g_m1[(size_t)BTOT * (HDIM / 2)];        // 33.5 MB
__device__ float  g_m2[BTOT * ODIM];
__device__ float  g_ss[BTOT * ODIM];

// ============================================================================
// Kernel 1: split W1. Bhi = fp16(w)*2^11 (exact scale), Blo = (w-fp16(w))*2^11.
// Final C = (x@Bhi^T + x@Blo^T) * 2^-11  ==  x@fp16(w)^T + x@residual^T.
// ============================================================================
__global__ void wsplit_kernel(const float* __restrict__ W1) {
    int idx = blockIdx.x * 256 + threadIdx.x;
    if (idx >= HDIM * KPAD) return;
    int n = idx / KPAD, k = idx % KPAD;
    float w = (k < JDIM) ? W1[n * JDIM + k] : 0.0f;
    __half hi = __float2half_rn(w);
    float hif = __half2float(hi);
    g_Bhi[idx] = __float2half_rn(hif * 2048.0f);          // exact (pow2 scale)
    g_Blo[idx] = __float2half_rn((w - hif) * 2048.0f);
}

// ============================================================================
// Kernel 2: pack x_t = (sample > rand_t) into 64-bit masks (13 words per row)
//   covers t in [t_off, t_off + len); grid = len*BTOT/8 blocks
// ============================================================================
__global__ __launch_bounds__(256)
void xbits_kernel(const float* __restrict__ sample,
                  const float* __restrict__ rand_u, int t_off) {
    const int lane = threadIdx.x & 31;
    const int wid = threadIdx.x >> 5;
    const size_t rl = (size_t)blockIdx.x * 8 + wid;
    const int t = t_off + (int)(rl / BTOT);
    const int b = (int)(rl % BTOT);
    const float* s = sample + (size_t)b * JDIM;
    const float* r = rand_u + ((size_t)t * BTOT + b) * JDIM;
    unsigned long long* dst = g_xbits + ((size_t)t * BTOT + b) * NKC;
    #pragma unroll
    for (int w = 0; w < NKC; w++) {
        int j0 = w * 64 + lane;
        int j1 = j0 + 32;
        bool b0 = (j0 < JDIM) && (s[j0] > r[j0]);
        bool b1 = (j1 < JDIM) && (s[j1] > r[j1]);
        unsigned lo = __ballot_sync(0xffffffffu, b0);
        unsigned hi = __ballot_sync(0xffffffffu, b1);
        if (lane == 0)
            dst[w] = ((unsigned long long)hi << 32) | (unsigned long long)lo;
    }
}

// ============================================================================
// MMA / ldmatrix / cp.async helpers (portable PTX)
// ============================================================================
__device__ __forceinline__ void mma16816(float* c, const uint32_t* a,
                                         uint32_t b0, uint32_t b1) {
    asm volatile(
        "mma.sync.aligned.m16n8k16.row.col.f32.f16.f16.f32 "
        "{%0,%1,%2,%3}, {%4,%5,%6,%7}, {%8,%9}, {%0,%1,%2,%3};"
        : "+f"(c[0]), "+f"(c[1]), "+f"(c[2]), "+f"(c[3])
        : "r"(a[0]), "r"(a[1]), "r"(a[2]), "r"(a[3]), "r"(b0), "r"(b1));
}

#define LDSM_X4(r0, r1, r2, r3, addr) \
    asm volatile("ldmatrix.sync.aligned.m8n8.x4.shared.b16 {%0,%1,%2,%3}, [%4];" \
                 : "=r"(r0), "=r"(r1), "=r"(r2), "=r"(r3) : "r"(addr))

#define CP_ASYNC16(saddr, gptr) \
    asm volatile("cp.async.cg.shared.global [%0], [%1], 16;" \
                 :: "r"(saddr), "l"(gptr) : "memory")
#define CP_COMMIT() asm volatile("cp.async.commit_group;" ::: "memory")
#define CP_WAIT1()  asm volatile("cp.async.wait_group 1;" ::: "memory")

__device__ __forceinline__ uint32_t smem_u32(const void* p) {
    uint32_t a;
    asm("{ .reg .u64 t; cvta.to.shared.u64 t, %1; cvt.u32.u64 %0, t; }"
        : "=r"(a) : "l"(p));
    return a;
}

// 2 x-bits at (pos, pos+1) -> packed fp16 pair {0/1, 0/1}
__device__ __forceinline__ uint32_t pair_to_h2(uint32_t s, int pos) {
    uint32_t b = s >> pos;
    return ((b & 1u) * 0x3C00u) | ((b & 2u) * 0x1E000000u);
}

// ============================================================================
// Kernel 3: fused single-pass HMMA GEMM (MMA order identical to round 11).
//   B is cp.async 3-stage (issued 2 kb ahead; wait_group 1 => no wait stall).
//   A is 2-stage (ALU-decoded + STS, protected by per-kb barrier).
//   grid (32*len, 8), block 512; writes C at absolute t.
// ============================================================================
__global__ __launch_bounds__(GT)
void gemm_kernel(int t0) {
    extern __shared__ char smem[];
    unsigned long long* xw = (unsigned long long*)smem;     // [256][13]
    const uint32_t sbase = smem_u32(smem);

    const int tid = threadIdx.x;
    const int lane = tid & 31;
    const int wid = tid >> 5;           // 0..15
    const int g = lane >> 2;            // 0..7
    const int t4 = lane & 3;            // 0..3
    const int tsh = t4 * 2;
    const int mwarp = wid & 7;          // 0..7 -> 32-row M group
    const int nwarp = wid >> 3;         // 0..1 -> 64-col N group

    const int tl = blockIdx.x >> 5;          // local t within chunk
    const int btile = blockIdx.x & 31;       // 0..31
    const int nb = blockIdx.y;               // 0..7
    const int tglob = t0 + tl;

    // decode thread mapping: row = tid>>1, half-word = tid&1
    const int drow = tid >> 1;
    const int dh = tid & 1;

    // ldmatrix per-lane row/byte offsets
    const uint32_t a_off = (uint32_t)((lane & 15) * PITCH + (lane >> 4) * 16);
    const uint32_t b_off = (uint32_t)
        (((lane & 7) + ((lane >> 4) << 3)) * PITCH + (((lane >> 3) & 1) << 4));

    // B staging indices (2 x 16B lines per tile per thread)
    const int br0 = tid >> 3, bq0 = tid & 7;
    const int br1 = (tid + GT) >> 3, bq1 = (tid + GT) & 7;

    const char* BgH = (const char*)(g_Bhi + (size_t)nb * NT * KPAD);
    const char* BgL = (const char*)(g_Blo + (size_t)nb * NT * KPAD);

    // ---- stage all x-bit words for this 256-row m-tile ----
    {
        const unsigned long long* src =
            g_xbits + ((size_t)tglob * BTOT + (size_t)btile * MT) * NKC;
        #pragma unroll
        for (int i = 0; i < 7; i++) {
            int idx = tid + i * GT;
            if (idx < MT * NKC) xw[idx] = src[idx];
        }
    }
    __syncthreads();

    float acc[2][8][4];
    #pragma unroll
    for (int mm = 0; mm < 2; mm++)
        #pragma unroll
        for (int nn = 0; nn < 8; nn++)
            #pragma unroll
            for (int q = 0; q < 4; q++) acc[mm][nn][q] = 0.0f;

    // ---- prologue: A(0) decode; B(0) and B(1) async stages ----
    {
        uint32_t bits = (uint32_t)(xw[drow * NKC + 0] >> (dh << 5));
        uint4* adst = (uint4*)(smem + OFF_A0 + drow * PITCH + dh * 64);
        #pragma unroll
        for (int q = 0; q < 4; q++) {
            uint4 v;
            v.x = pair_to_h2(bits, q * 8 + 0);
            v.y = pair_to_h2(bits, q * 8 + 2);
            v.z = pair_to_h2(bits, q * 8 + 4);
            v.w = pair_to_h2(bits, q * 8 + 6);
            adst[q] = v;
        }
        #pragma unroll
        for (int kb = 0; kb < 2; kb++) {
            const uint32_t bh = sbase + BBASE + kb * BSTAGE;
            const uint32_t bl = bh + BTILE;
            const char* srcH = BgH + kb * 128;
            const char* srcL = BgL + kb * 128;
            CP_ASYNC16(bh + br0 * PITCH + bq0 * 16,
                       srcH + (size_t)br0 * (KPAD * 2) + bq0 * 16);
            CP_ASYNC16(bh + br1 * PITCH + bq1 * 16,
                       srcH + (size_t)br1 * (KPAD * 2) + bq1 * 16);
            CP_ASYNC16(bl + br0 * PITCH + bq0 * 16,
                       srcL + (size_t)br0 * (KPAD * 2) + bq0 * 16);
            CP_ASYNC16(bl + br1 * PITCH + bq1 * 16,
                       srcL + (size_t)br1 * (KPAD * 2) + bq1 * 16);
            CP_COMMIT();
        }
    }

    int s = 0;                               // B stage index = kb % 3
    #pragma unroll 1
    for (int kb = 0; kb < NKC; kb++) {
        const int abuf = kb & 1;
        CP_WAIT1();                          // B(kb) landed (issued 2 kb ago)
        __syncthreads();

        // ---- MMAs on current buffers (order identical to round 11) ----
        const uint32_t Ab  = sbase + (abuf ? OFF_A1 : OFF_A0);
        const uint32_t BbH = sbase + BBASE + s * BSTAGE;
        const uint32_t BbL = BbH + BTILE;
        const uint32_t a0_addr = Ab + (uint32_t)(mwarp * 32) * PITCH + a_off;
        const uint32_t a1_addr = a0_addr + 16 * PITCH;
        const uint32_t bh_addr = BbH + (uint32_t)(nwarp * 64) * PITCH + b_off;
        const uint32_t bl_addr = BbL + (uint32_t)(nwarp * 64) * PITCH + b_off;

        #pragma unroll
        for (int ks = 0; ks < 4; ks++) {
            uint32_t A0[4], A1[4];
            LDSM_X4(A0[0], A0[1], A0[2], A0[3], a0_addr + ks * 32);
            LDSM_X4(A1[0], A1[1], A1[2], A1[3], a1_addr + ks * 32);
            #pragma unroll
            for (int np = 0; np < 4; np++) {
                uint32_t B0, B1, B2, B3;
                LDSM_X4(B0, B1, B2, B3,
                        bh_addr + (uint32_t)(np * 16) * PITCH + ks * 32);
                mma16816(acc[0][np * 2],     A0, B0, B1);
                mma16816(acc[1][np * 2],     A1, B0, B1);
                mma16816(acc[0][np * 2 + 1], A0, B2, B3);
                mma16816(acc[1][np * 2 + 1], A1, B2, B3);
            }
            #pragma unroll
            for (int np = 0; np < 4; np++) {
                uint32_t B0, B1, B2, B3;
                LDSM_X4(B0, B1, B2, B3,
                        bl_addr + (uint32_t)(np * 16) * PITCH + ks * 32);
                mma16816(acc[0][np * 2],     A0, B0, B1);
                mma16816(acc[1][np * 2],     A1, B0, B1);
                mma16816(acc[0][np * 2 + 1], A0, B2, B3);
                mma16816(acc[1][np * 2 + 1], A1, B2, B3);
            }
        }

        // ---- stage A(kb+1) (STS) and B(kb+2) (async, 2 ahead) ----
        if (kb + 1 < NKC) {
            const int aoff = (abuf ? OFF_A0 : OFF_A1);
            uint32_t bits = (uint32_t)(xw[drow * NKC + kb + 1] >> (dh << 5));
            uint4* adst = (uint4*)(smem + aoff + drow * PITCH + dh * 64);
            #pragma unroll
            for (int q = 0; q < 4; q++) {
                uint4 v;
                v.x = pair_to_h2(bits, q * 8 + 0);
                v.y = pair_to_h2(bits, q * 8 + 2);
                v.z = pair_to_h2(bits, q * 8 + 4);
                v.w = pair_to_h2(bits, q * 8 + 6);
                adst[q] = v;
            }
        }
        if (kb + 2 < NKC) {
            const int s2i = (s + 2 >= 3) ? (s - 1) : (s + 2);   // (s+2)%3
            const uint32_t bh = sbase + BBASE + s2i * BSTAGE;
            const uint32_t bl = bh + BTILE;
            const char* srcH = BgH + (kb + 2) * 128;
            const char* srcL = BgL + (kb + 2) * 128;
            CP_ASYNC16(bh + br0 * PITCH + bq0 * 16,
                       srcH + (size_t)br0 * (KPAD * 2) + bq0 * 16);
            CP_ASYNC16(bh + br1 * PITCH + bq1 * 16,
                       srcH + (size_t)br1 * (KPAD * 2) + bq1 * 16);
            CP_ASYNC16(bl + br0 * PITCH + bq0 * 16,
                       srcL + (size_t)br0 * (KPAD * 2) + bq0 * 16);
            CP_ASYNC16(bl + br1 * PITCH + bq1 * 16,
                       srcL + (size_t)br1 * (KPAD * 2) + bq1 * 16);
        }
        CP_COMMIT();                          // always commit (keeps accounting)
        s = (s + 1 >= 3) ? 0 : (s + 1);
    }

    // ---- epilogue: C = acc * 2^-11 (streaming stores, absolute t) ----
    float* Cg = g_C;
    const size_t rowbase = (size_t)tglob * BTOT + (size_t)btile * MT + mwarp * 32;
    const int colbase = nb * NT + nwarp * 64 + tsh;
    #pragma unroll
    for (int mm = 0; mm < 2; mm++) {
        float* r0 = Cg + (rowbase + mm * 16 + g) * HDIM + colbase;
        float* r1 = r0 + 8 * HDIM;
        #pragma unroll
        for (int nn = 0; nn < 8; nn++) {
            __stcs((float2*)(r0 + nn * 8),
                   make_float2(acc[mm][nn][0] * (1.0f / 2048.0f),
                               acc[mm][nn][1] * (1.0f / 2048.0f)));
            __stcs((float2*)(r1 + nn * 8),
                   make_float2(acc[mm][nn][2] * (1.0f / 2048.0f),
                               acc[mm][nn][3] * (1.0f / 2048.0f)));
        }
    }
}

// Packed fp32x2 helpers (scan kernel)
#define FMA_DECAY_F32X2(acc, dec2, c2) \
    asm("fma.rn.f32x2 %0, %0, %1, %2;" : "+l"(acc) : "l"(dec2), "l"(c2))
#define PACK64(lo32, hi32, dst) \
    asm("mov.b64 %0, {%1, %2};" : "=l"(dst) : "r"(lo32), "r"(hi32))

// ============================================================================
// Kernel 4: sequential membrane scan over [t0, t0+len).
//   Identical numerics/layout to round 11; C indexed by absolute t.
// ============================================================================
#define BM2 8
#define W2P 12
__global__ __launch_bounds__(256, 2)
void scan_kernel(const float* __restrict__ W2, float* __restrict__ out,
                 int t0, int len) {
    __shared__ float W2t[HDIM * W2P];         // 48 KB: [h][o(0..9), pad, pad]

    const int tid = threadIdx.x;
    const int lane = tid & 31;
    const int row = tid >> 5;                 // warp id == batch row in tile
    const int rowbase = blockIdx.x * BM2;
    const float* Cg = g_C + (size_t)t0 * BTOT * HDIM;

    for (int i = tid; i < HDIM * W2P; i += 256) {
        int h = i / W2P, o = i % W2P;
        W2t[i] = (o < ODIM) ? W2[o * HDIM + h] : 0.0f;
    }

    // ---- state ----
    unsigned long long acc[16];
    float m2r[ODIM], ssr[ODIM];
    const size_t mbase = ((size_t)(rowbase + row) * 32 + lane) * 16;
    if (t0 == 0) {
        #pragma unroll
        for (int i = 0; i < 16; i++) acc[i] = 0ull;
        #pragma unroll
        for (int o = 0; o < ODIM; o++) { m2r[o] = 0.0f; ssr[o] = 0.0f; }
    } else {
        #pragma unroll
        for (int i = 0; i < 16; i++) acc[i] = g_m1[mbase + i];
        #pragma unroll
        for (int o = 0; o < ODIM; o++) {
            m2r[o] = g_m2[(rowbase + row) * ODIM + o];
            ssr[o] = g_ss[(rowbase + row) * ODIM + o];
        }
    }
    const unsigned long long DEC2 = 0x3E4CCCCD3E4CCCCDull;   // (0.2f, 0.2f)
    __syncthreads();   // W2t ready

    // coalesced base: lane*4 floats; q-th load at +q*128 floats
    const size_t rowoff = (size_t)(rowbase + row) * HDIM + lane * 4;
    const int hb = ((lane >> 2) << 7) + (lane & 3);   // layer-2 lane h-base

    uint4 bufA[8], bufB[8];
    {   // prime: load C_{t0}
        const float* p = Cg + rowoff;
        #pragma unroll
        for (int q = 0; q < 8; q++) bufA[q] = __ldcs((const uint4*)(p + q * 128));
    }

    #pragma unroll 1
    for (int tt = 0; tt < len; tt++) {
        uint4* cur = (tt & 1) ? bufB : bufA;
        uint4* nxt = (tt & 1) ? bufA : bufB;
        if (tt + 1 < len) {
            const float* p = Cg + (size_t)(tt + 1) * BTOT * HDIM + rowoff;
            #pragma unroll
            for (int q = 0; q < 8; q++) nxt[q] = __ldcs((const uint4*)(p + q * 128));
        }

        // ---- m1 = decay*m1 + C_t; spike; reset; pack 32 bits ----
        unsigned word = 0;
        #pragma unroll
        for (int q = 0; q < 8; q++) {
            unsigned long long c0, c1;
            PACK64(cur[q].x, cur[q].y, c0);
            PACK64(cur[q].z, cur[q].w, c1);
            FMA_DECAY_F32X2(acc[2 * q],     DEC2, c0);
            FMA_DECAY_F32X2(acc[2 * q + 1], DEC2, c1);
        }
        #pragma unroll
        for (int i = 0; i < 16; i++) {
            float flo = __uint_as_float((unsigned)(acc[i] & 0xffffffffull));
            float fhi = __uint_as_float((unsigned)(acc[i] >> 32));
            if (flo > THRESH_F) { word |= 1u << (2 * i);     flo = 0.0f; }
            if (fhi > THRESH_F) { word |= 1u << (2 * i + 1); fhi = 0.0f; }
            acc[i] = ((unsigned long long)__float_as_uint(fhi) << 32) |
                     (unsigned long long)__float_as_uint(flo);
        }

        // ---- layer 2: lane i consumes bit i of lane-k's word ----
        float4 d0 = make_float4(0.f, 0.f, 0.f, 0.f);
        float4 d1 = make_float4(0.f, 0.f, 0.f, 0.f);
        float4 d2 = make_float4(0.f, 0.f, 0.f, 0.f);
        #pragma unroll 4
        for (int k = 0; k < 32; k++) {
            const unsigned wmask = __shfl_sync(0xffffffffu, word, k);
            if ((wmask >> lane) & 1u) {
                const int h = hb + 4 * k;     // 128*(lane>>2) + 4k + (lane&3)
                const float4* p = (const float4*)(W2t + h * W2P);
                float4 x0 = p[0], x1 = p[1], x2 = p[2];
                d0.x += x0.x; d0.y += x0.y; d0.z += x0.z; d0.w += x0.w;
                d1.x += x1.x; d1.y += x1.y; d1.z += x1.z; d1.w += x1.w;
                d2.x += x2.x; d2.y += x2.y;               // o8, o9
            }
        }
        float dot[ODIM] = { d0.x, d0.y, d0.z, d0.w,
                            d1.x, d1.y, d1.z, d1.w, d2.x, d2.y };
        #pragma unroll
        for (int o = 0; o < ODIM; o++) {
            float v = dot[o];
            v += __shfl_xor_sync(0xffffffffu, v, 16);
            v += __shfl_xor_sync(0xffffffffu, v, 8);
            v += __shfl_xor_sync(0xffffffffu, v, 4);
            v += __shfl_xor_sync(0xffffffffu, v, 2);
            v += __shfl_xor_sync(0xffffffffu, v, 1);
            float mm = 0.2f * m2r[o] + v;         // identical on all lanes
            if (mm > THRESH_F) { ssr[o] += 1.0f; mm = 0.0f; }
            m2r[o] = mm;
        }
    }

    // ---- spill state; write output on the final chunk ----
    #pragma unroll
    for (int i = 0; i < 16; i++) g_m1[mbase + i] = acc[i];
    if (lane == 0) {
        #pragma unroll
        for (int o = 0; o < ODIM; o++) {
            g_m2[(rowbase + row) * ODIM + o] = m2r[o];
            g_ss[(rowbase + row) * ODIM + o] = ssr[o];
        }
        if (t0 + len >= TSTEPS) {
            #pragma unroll
            for (int o = 0; o < ODIM; o++)
                out[(size_t)(rowbase + row) * ODIM + o] = ssr[o] * (1.0f / TSTEPS);
        }
    }
}

// ============================================================================
extern "C" void kernel_launch(void* const* d_in, const int* in_sizes, int n_in,
                              void* d_out, int out_size) {
    const float* input  = (const float*)d_in[0];   // [8192,1,28,28] == [8192,784]
    const float* rand_u = (const float*)d_in[1];   // [50,8192,784]
    const float* W1     = (const float*)d_in[2];   // [1024,784]
    const float* W2     = (const float*)d_in[3];   // [10,1024]
    float* out = (float*)d_out;                    // [8192,10]

    // one-time setup (first call is the uncaptured correctness run)
    static bool init_done = false;
    static cudaStream_t s2 = nullptr;
    static cudaEvent_t evX = nullptr, ev0 = nullptr, ev1 = nullptr, ev2 = nullptr;
    if (!init_done) {
        cudaFuncSetAttribute(gemm_kernel,
                             cudaFuncAttributeMaxDynamicSharedMemorySize, SMEM_G);
        cudaStreamCreateWithFlags(&s2, cudaStreamNonBlocking);
        cudaEventCreateWithFlags(&evX, cudaEventDisableTiming);
        cudaEventCreateWithFlags(&ev0, cudaEventDisableTiming);
        cudaEventCreateWithFlags(&ev1, cudaEventDisableTiming);
        cudaEventCreateWithFlags(&ev2, cudaEventDisableTiming);
        init_done = true;
    }

    // stream0: wsplit -> xbits[0,C0) -> gemm0 -> scan0 -> scan1 -> scan2
    // s2:      xbits[C0,50) (overlaps gemm0) -> gemm1 -> gemm2
    wsplit_kernel<<<(HDIM * KPAD + 255) / 256, 256>>>(W1);
    xbits_kernel<<<C0 * BTOT / 8, 256>>>(input, rand_u, 0);
    cudaEventRecord(evX, 0);

    gemm_kernel<<<dim3(32 * C0, HDIM / NT), GT, SMEM_G>>>(0);
    cudaEventRecord(ev0, 0);

    cudaStreamWaitEvent(s2, evX, 0);
    xbits_kernel<<<(C1 + C2) * BTOT / 8, 256, 0, s2>>>(input, rand_u, C0);
    cudaStreamWaitEvent(s2, ev0, 0);
    gemm_kernel<<<dim3(32 * C1, HDIM / NT), GT, SMEM_G, s2>>>(C0);
    cudaEventRecord(ev1, s2);
    gemm_kernel<<<dim3(32 * C2, HDIM / NT), GT, SMEM_G, s2>>>(C0 + C1);
    cudaEventRecord(ev2, s2);

    scan_kernel<<<BTOT / BM2, 256>>>(W2, out, 0, C0);
    cudaStreamWaitEvent(0, ev1, 0);
    scan_kernel<<<BTOT / BM2, 256>>>(W2, out, C0, C1);
    cudaStreamWaitEvent(0, ev2, 0);
    scan_kernel<<<BTOT / BM2, 256>>>(W2, out, C0 + C1, C2);
}